// round 3
// baseline (speedup 1.0000x reference)
#include <cuda_runtime.h>
#include <cuda_bf16.h>

// ---------------------------------------------------------------------------
// Problem constants
// ---------------------------------------------------------------------------
#define Bn  4
#define Sn  1024
#define Dn  1024
#define Hn  16
#define DKn 64

// ---------------------------------------------------------------------------
// Device scratch
// ---------------------------------------------------------------------------
__device__ float g_q[(size_t)Bn * Hn * Sn * DKn];      // [B,H,S,DK]
__device__ float g_k[(size_t)Bn * Hn * Sn * DKn];
__device__ float g_v[(size_t)Bn * Hn * Sn * DKn];
__device__ float g_biasT[(size_t)Bn * Hn * Sn * Sn];   // [B,H,S,S]
__device__ float g_ctx[(size_t)Bn * Sn * Dn];          // [B,S,D]
__device__ unsigned char g_mask[Bn * Sn];

// ---------------------------------------------------------------------------
// Helpers
// ---------------------------------------------------------------------------
__device__ __forceinline__ unsigned f2tf32(float x) {
    unsigned r;
    asm("cvt.rna.tf32.f32 %0, %1;" : "=r"(r) : "f"(x));
    return r;
}

__device__ __forceinline__ void mma_tf32(float c[4], const unsigned a[4], const unsigned b[2]) {
    asm volatile(
        "mma.sync.aligned.m16n8k8.row.col.f32.tf32.tf32.f32 "
        "{%0,%1,%2,%3},{%4,%5,%6,%7},{%8,%9},{%0,%1,%2,%3};\n"
        : "+f"(c[0]), "+f"(c[1]), "+f"(c[2]), "+f"(c[3])
        : "r"(a[0]), "r"(a[1]), "r"(a[2]), "r"(a[3]), "r"(b[0]), "r"(b[1]));
}

__device__ __forceinline__ float2 ldcs2(const float* p) {
    float2 r;
    asm volatile("ld.global.cs.v2.f32 {%0,%1}, [%2];" : "=f"(r.x), "=f"(r.y) : "l"(p));
    return r;
}

// ---------------------------------------------------------------------------
// Mask normalization
// ---------------------------------------------------------------------------
__global__ void mask_prep_kernel(const void* __restrict__ mraw) {
    __shared__ int flags[2];
    if (threadIdx.x < 2) flags[threadIdx.x] = 0;
    __syncthreads();
    const unsigned* w = (const unsigned*)mraw;
    for (int i = threadIdx.x; i < 1024; i += blockDim.x) {
        unsigned v = w[i];
        if (v > 1u) flags[0] = 1;
        if (v != 0u && v != 0x3F800000u) flags[1] = 1;
    }
    __syncthreads();
    int mode = flags[0] ? (flags[1] ? 0 : 2) : 1;
    for (int i = threadIdx.x; i < Bn * Sn; i += blockDim.x) {
        unsigned char v;
        if (mode == 1)      v = (((const int*)mraw)[i] != 0);
        else if (mode == 2) v = (((const float*)mraw)[i] != 0.f);
        else                v = (((const unsigned char*)mraw)[i] != 0);
        g_mask[i] = v;
    }
}

// ---------------------------------------------------------------------------
// Bias transpose [B,S,S,H] -> [B,H,S,S], streaming hints both sides.
// ---------------------------------------------------------------------------
__global__ void bias_tr_kernel(const float* __restrict__ bias) {
    __shared__ float t[16][129];
    const int k0 = blockIdx.x * 128;
    const int q  = blockIdx.y;
    const int b  = blockIdx.z;
    const float* src = bias + ((size_t)(b * Sn + q) * Sn + k0) * Hn;
    for (int i = threadIdx.x; i < 2048; i += 256) {
        int kk = i >> 4, hh = i & 15;
        float v;
        asm volatile("ld.global.cs.f32 %0, [%1];" : "=f"(v) : "l"(src + i));
        t[hh][kk] = v;
    }
    __syncthreads();
    for (int i = threadIdx.x; i < 2048; i += 256) {
        int hh = i >> 7, kk = i & 127;
        float v = t[hh][kk];
        float* dst = &g_biasT[((size_t)(b * Hn + hh) * Sn + q) * Sn + k0 + kk];
        asm volatile("st.global.cs.f32 [%0], %1;" :: "l"(dst), "f"(v));
    }
}

// ---------------------------------------------------------------------------
// TN GEMM: C[M,N] = A[M,1024] * W[N,1024]^T + bias[n]
// 128x128x32 CTA tile, 256 threads, double-buffered smem,
// paired-column smem layout -> LDS.64 fragment loads.
// ---------------------------------------------------------------------------
#define GS   40            // smem stride (words) for a 32-col k-tile
#define GBUF (128 * GS)    // one buffer: 5120 words
#define SMEM_GEMM (4 * GBUF * 4)   // 81920 B

template <int MODE>
__device__ __forceinline__ void gemm_core(unsigned* __restrict__ sbuf,
                                          const float* __restrict__ A,
                                          const float* __restrict__ W,
                                          const float* __restrict__ bvec,
                                          float* __restrict__ out,
                                          int m0, int n0) {
    unsigned* sA = sbuf;
    unsigned* sW = sbuf + 2 * GBUF;

    const int tid  = threadIdx.x;
    const int lane = tid & 31;
    const int warp = tid >> 5;
    const int j    = lane & 3;
    const int wm = (warp >> 2) * 64;
    const int wn = (warp & 3) * 32;

    float acc[4][4][4];
#pragma unroll
    for (int mt = 0; mt < 4; mt++)
#pragma unroll
        for (int nt = 0; nt < 4; nt++)
#pragma unroll
            for (int q = 0; q < 4; q++) acc[mt][nt][q] = 0.f;

    float4 ra[4], rw[4];
#pragma unroll
    for (int i = 0; i < 4; i++) {
        int task = i * 256 + tid;
        int row = task >> 3, c4 = task & 7;
        ra[i] = *(const float4*)(A + (size_t)(m0 + row) * Dn + c4 * 4);
        rw[i] = *(const float4*)(W + (size_t)(n0 + row) * Dn + c4 * 4);
    }

    for (int kt = 0; kt < 32; kt++) {
        unsigned* cA = sA + (kt & 1) * GBUF;
        unsigned* cW = sW + (kt & 1) * GBUF;
#pragma unroll
        for (int i = 0; i < 4; i++) {
            int task = i * 256 + tid;
            int row = task >> 3, c4 = task & 7;
            int base = row * GS + ((c4 >> 1) << 3) + (c4 & 1);
            cA[base + 0] = f2tf32(ra[i].x); cA[base + 2] = f2tf32(ra[i].y);
            cA[base + 4] = f2tf32(ra[i].z); cA[base + 6] = f2tf32(ra[i].w);
            cW[base + 0] = f2tf32(rw[i].x); cW[base + 2] = f2tf32(rw[i].y);
            cW[base + 4] = f2tf32(rw[i].z); cW[base + 6] = f2tf32(rw[i].w);
        }
        __syncthreads();

        if (kt < 31) {
            int kb = (kt + 1) * 32;
#pragma unroll
            for (int i = 0; i < 4; i++) {
                int task = i * 256 + tid;
                int row = task >> 3, c4 = task & 7;
                ra[i] = *(const float4*)(A + (size_t)(m0 + row) * Dn + kb + c4 * 4);
                rw[i] = *(const float4*)(W + (size_t)(n0 + row) * Dn + kb + c4 * 4);
            }
        }

#pragma unroll
        for (int ks = 0; ks < 4; ks++) {
            const int off = ks * 8 + 2 * j;
            unsigned afr[4][4];
#pragma unroll
            for (int mt = 0; mt < 4; mt++) {
                int r = wm + mt * 16 + (lane >> 2);
                uint2 u0 = *(const uint2*)&cA[r * GS + off];
                uint2 u1 = *(const uint2*)&cA[(r + 8) * GS + off];
                afr[mt][0] = u0.x; afr[mt][1] = u1.x;
                afr[mt][2] = u0.y; afr[mt][3] = u1.y;
            }
            unsigned bfr[4][2];
#pragma unroll
            for (int nt = 0; nt < 4; nt++) {
                int r = wn + nt * 8 + (lane >> 2);
                uint2 ub = *(const uint2*)&cW[r * GS + off];
                bfr[nt][0] = ub.x; bfr[nt][1] = ub.y;
            }
#pragma unroll
            for (int mt = 0; mt < 4; mt++)
#pragma unroll
                for (int nt = 0; nt < 4; nt++)
                    mma_tf32(acc[mt][nt], afr[mt], bfr[nt]);
        }
    }
    __syncthreads();

#pragma unroll
    for (int mt = 0; mt < 4; mt++) {
#pragma unroll
        for (int nt = 0; nt < 4; nt++) {
            int row = m0 + wm + mt * 16 + (lane >> 2);
            int col = n0 + wn + nt * 8 + (j << 1);
            float b0 = bvec[col], b1 = bvec[col + 1];
            float2 v0 = make_float2(acc[mt][nt][0] + b0, acc[mt][nt][1] + b1);
            float2 v1 = make_float2(acc[mt][nt][2] + b0, acc[mt][nt][3] + b1);
            if (MODE == 0) {
                *(float2*)(out + (size_t)row * Dn + col) = v0;
                *(float2*)(out + (size_t)(row + 8) * Dn + col) = v1;
            } else {
                int hh = col >> 6, dk = col & 63;
                int bb0 = row >> 10, s0 = row & 1023;
                int r8 = row + 8;
                int bb1 = r8 >> 10, s1 = r8 & 1023;
                *(float2*)(out + ((size_t)(bb0 * Hn + hh) * Sn + s0) * DKn + dk) = v0;
                *(float2*)(out + ((size_t)(bb1 * Hn + hh) * Sn + s1) * DKn + dk) = v1;
            }
        }
    }
}

__global__ void __launch_bounds__(256) qkv_proj_kernel(
    const float* __restrict__ Xq, const float* __restrict__ Xk, const float* __restrict__ Xv,
    const float* __restrict__ Wq, const float* __restrict__ Wk, const float* __restrict__ Wv,
    const float* __restrict__ bq, const float* __restrict__ bk, const float* __restrict__ bv) {
    extern __shared__ unsigned sbuf[];
    int z = blockIdx.z;
    const float* A = (z == 0) ? Xq : (z == 1) ? Xk : Xv;
    const float* W = (z == 0) ? Wq : (z == 1) ? Wk : Wv;
    const float* bb = (z == 0) ? bq : (z == 1) ? bk : bv;
    float* out = (z == 0) ? g_q : (z == 1) ? g_k : g_v;
    gemm_core<1>(sbuf, A, W, bb, out, blockIdx.y * 128, blockIdx.x * 128);
}

__global__ void __launch_bounds__(256) outproj_kernel(
    const float* __restrict__ Wo, const float* __restrict__ bo, float* __restrict__ out) {
    extern __shared__ unsigned sbuf[];
    gemm_core<0>(sbuf, g_ctx, Wo, bo, out, blockIdx.y * 128, blockIdx.x * 128);
}

// ---------------------------------------------------------------------------
// Flash attention v2: CTA = 128 q-rows x head. 256 threads, 8 warps.
// Q fragments register-resident; K/V register-staged; paired-col smem.
// ---------------------------------------------------------------------------
#define AKS 72
#define ASZ_K (64 * AKS)
#define ASZ_V (64 * AKS)
#define ASZ_P (128 * AKS)
#define SMEM_ATTN ((ASZ_K + ASZ_V + ASZ_P) * 4 + 64)

__global__ void __launch_bounds__(256) attn_kernel() {
    extern __shared__ unsigned sm[];
    unsigned* sK = sm;
    unsigned* sV = sm + ASZ_K;
    unsigned* sP = sm + ASZ_K + ASZ_V;
    unsigned char* smk = (unsigned char*)(sm + ASZ_K + ASZ_V + ASZ_P);

    const int tid = threadIdx.x, lane = tid & 31, warp = tid >> 5;
    const int j = lane & 3;
    const int rq = warp * 16 + (lane >> 2);
    const int q0 = blockIdx.x * 128;
    const int h = blockIdx.y, b = blockIdx.z;

    const size_t headoff = (size_t)(b * Hn + h) * Sn * DKn;
    const float* Qg = g_q + headoff + (size_t)q0 * DKn;
    const float* Kg = g_k + headoff;
    const float* Vg = g_v + headoff;
    const float* Bg = g_biasT + ((size_t)(b * Hn + h) * Sn + q0) * Sn;
    const unsigned char* Mg = g_mask + b * Sn;

    // Stage Q tile into sP (paired-col layout), then pull fragments to regs.
#pragma unroll
    for (int i = 0; i < 8; i++) {
        int task = i * 256 + tid;
        int row = task >> 4, c4 = task & 15;
        float4 v = *(const float4*)(Qg + (size_t)row * DKn + c4 * 4);
        int base = row * AKS + ((c4 >> 1) << 3) + (c4 & 1);
        sP[base + 0] = f2tf32(v.x); sP[base + 2] = f2tf32(v.y);
        sP[base + 4] = f2tf32(v.z); sP[base + 6] = f2tf32(v.w);
    }
    __syncthreads();

    unsigned qfr[8][4];
#pragma unroll
    for (int ks = 0; ks < 8; ks++) {
        int off = ks * 8 + 2 * j;
        uint2 u0 = *(const uint2*)&sP[rq * AKS + off];
        uint2 u1 = *(const uint2*)&sP[(rq + 8) * AKS + off];
        qfr[ks][0] = u0.x; qfr[ks][1] = u1.x; qfr[ks][2] = u0.y; qfr[ks][3] = u1.y;
    }

    const int mq0 = Mg[q0 + rq];
    const int mq1 = Mg[q0 + rq + 8];

    float mrow0 = -1e30f, mrow1 = -1e30f, lrow0 = 0.f, lrow1 = 0.f;
    float o[8][4];
#pragma unroll
    for (int nt = 0; nt < 8; nt++)
#pragma unroll
        for (int q = 0; q < 4; q++) o[nt][q] = 0.f;

    float4 kst[4], vst[4];
#pragma unroll
    for (int i = 0; i < 4; i++) {
        int task = i * 256 + tid;
        int row = task >> 4, c4 = task & 15;
        kst[i] = *(const float4*)(Kg + (size_t)row * DKn + c4 * 4);
        vst[i] = *(const float4*)(Vg + (size_t)row * DKn + c4 * 4);
    }

    for (int kt = 0; kt < 16; kt++) {
        const int kv0 = kt * 64;
        __syncthreads();  // previous PV done; sK/sV free

#pragma unroll
        for (int i = 0; i < 4; i++) {
            int task = i * 256 + tid;
            int row = task >> 4, c4 = task & 15;
            int base = row * AKS + ((c4 >> 1) << 3) + (c4 & 1);
            sK[base + 0] = f2tf32(kst[i].x); sK[base + 2] = f2tf32(kst[i].y);
            sK[base + 4] = f2tf32(kst[i].z); sK[base + 6] = f2tf32(kst[i].w);
            int vb = row * AKS + c4 * 4;
            *(uint4*)&sV[vb] = make_uint4(f2tf32(vst[i].x), f2tf32(vst[i].y),
                                          f2tf32(vst[i].z), f2tf32(vst[i].w));
        }
        if (tid < 64) smk[tid] = Mg[kv0 + tid];
        __syncthreads();

        if (kt < 15) {
            const int kb = kv0 + 64;
#pragma unroll
            for (int i = 0; i < 4; i++) {
                int task = i * 256 + tid;
                int row = task >> 4, c4 = task & 15;
                kst[i] = *(const float4*)(Kg + (size_t)(kb + row) * DKn + c4 * 4);
                vst[i] = *(const float4*)(Vg + (size_t)(kb + row) * DKn + c4 * 4);
            }
        }

        // Bias prefetch (streaming)
        float2 bb0[8], bb1[8];
#pragma unroll
        for (int nt = 0; nt < 8; nt++) {
            int col = nt * 8 + (j << 1);
            bb0[nt] = ldcs2(Bg + (size_t)rq * Sn + kv0 + col);
            bb1[nt] = ldcs2(Bg + (size_t)(rq + 8) * Sn + kv0 + col);
        }

        // S = Q K^T
        float s[8][4];
#pragma unroll
        for (int nt = 0; nt < 8; nt++)
#pragma unroll
            for (int q = 0; q < 4; q++) s[nt][q] = 0.f;

#pragma unroll
        for (int ks = 0; ks < 8; ks++) {
            const int off = ks * 8 + 2 * j;
#pragma unroll
            for (int nt = 0; nt < 8; nt++) {
                int r = nt * 8 + (lane >> 2);
                uint2 ub = *(const uint2*)&sK[r * AKS + off];
                unsigned bfr[2] = {ub.x, ub.y};
                mma_tf32(s[nt], qfr[ks], bfr);
            }
        }

        // bias + scale + mask + online softmax
        float rmax0 = -1e30f, rmax1 = -1e30f;
#pragma unroll
        for (int nt = 0; nt < 8; nt++) {
            int col = nt * 8 + (j << 1);
            int k0ok = smk[col], k1ok = smk[col + 1];
            float v0 = (mq0 & k0ok) ? (s[nt][0] + bb0[nt].x) * 0.125f : -1e9f;
            float v1 = (mq0 & k1ok) ? (s[nt][1] + bb0[nt].y) * 0.125f : -1e9f;
            float v2 = (mq1 & k0ok) ? (s[nt][2] + bb1[nt].x) * 0.125f : -1e9f;
            float v3 = (mq1 & k1ok) ? (s[nt][3] + bb1[nt].y) * 0.125f : -1e9f;
            s[nt][0] = v0; s[nt][1] = v1; s[nt][2] = v2; s[nt][3] = v3;
            rmax0 = fmaxf(rmax0, fmaxf(v0, v1));
            rmax1 = fmaxf(rmax1, fmaxf(v2, v3));
        }
        rmax0 = fmaxf(rmax0, __shfl_xor_sync(0xffffffffu, rmax0, 1));
        rmax0 = fmaxf(rmax0, __shfl_xor_sync(0xffffffffu, rmax0, 2));
        rmax1 = fmaxf(rmax1, __shfl_xor_sync(0xffffffffu, rmax1, 1));
        rmax1 = fmaxf(rmax1, __shfl_xor_sync(0xffffffffu, rmax1, 2));

        float mnew0 = fmaxf(mrow0, rmax0), mnew1 = fmaxf(mrow1, rmax1);
        float alpha0 = __expf(mrow0 - mnew0), alpha1 = __expf(mrow1 - mnew1);
        mrow0 = mnew0; mrow1 = mnew1;

        float sum0 = 0.f, sum1 = 0.f;
#pragma unroll
        for (int nt = 0; nt < 8; nt++) {
            s[nt][0] = __expf(s[nt][0] - mnew0); sum0 += s[nt][0];
            s[nt][1] = __expf(s[nt][1] - mnew0); sum0 += s[nt][1];
            s[nt][2] = __expf(s[nt][2] - mnew1); sum1 += s[nt][2];
            s[nt][3] = __expf(s[nt][3] - mnew1); sum1 += s[nt][3];
        }
        sum0 += __shfl_xor_sync(0xffffffffu, sum0, 1);
        sum0 += __shfl_xor_sync(0xffffffffu, sum0, 2);
        sum1 += __shfl_xor_sync(0xffffffffu, sum1, 1);
        sum1 += __shfl_xor_sync(0xffffffffu, sum1, 2);
        lrow0 = lrow0 * alpha0 + sum0;
        lrow1 = lrow1 * alpha1 + sum1;

#pragma unroll
        for (int nt = 0; nt < 8; nt++) {
            o[nt][0] *= alpha0; o[nt][1] *= alpha0;
            o[nt][2] *= alpha1; o[nt][3] *= alpha1;
        }

        // P -> sP (rows are warp-private: syncwarp suffices)
        const int off0 = (j < 2) ? (4 * j) : (4 * j - 7);
#pragma unroll
        for (int nt = 0; nt < 8; nt++) {
            int b0i = rq * AKS + nt * 8;
            int b1i = (rq + 8) * AKS + nt * 8;
            sP[b0i + off0]     = f2tf32(s[nt][0]);
            sP[b0i + off0 + 2] = f2tf32(s[nt][1]);
            sP[b1i + off0]     = f2tf32(s[nt][2]);
            sP[b1i + off0 + 2] = f2tf32(s[nt][3]);
        }
        __syncwarp();

        // O += P V
#pragma unroll
        for (int ks = 0; ks < 8; ks++) {
            const int kk = ks * 8;
            const int off = kk + 2 * j;
            uint2 u0 = *(const uint2*)&sP[rq * AKS + off];
            uint2 u1 = *(const uint2*)&sP[(rq + 8) * AKS + off];
            unsigned afr[4] = {u0.x, u1.x, u0.y, u1.y};
#pragma unroll
            for (int nt = 0; nt < 8; nt++) {
                int n = nt * 8 + (lane >> 2);
                unsigned bfr[2] = {sV[(kk + j) * AKS + n], sV[(kk + 4 + j) * AKS + n]};
                mma_tf32(o[nt], afr, bfr);
            }
        }
    }

    // Epilogue
    float inv0 = 1.f / lrow0, inv1 = 1.f / lrow1;
    float* Cg = g_ctx + ((size_t)b * Sn + q0) * Dn + h * DKn;
#pragma unroll
    for (int nt = 0; nt < 8; nt++) {
        int col = nt * 8 + (j << 1);
        *(float2*)(Cg + (size_t)rq * Dn + col) =
            make_float2(o[nt][0] * inv0, o[nt][1] * inv0);
        *(float2*)(Cg + (size_t)(rq + 8) * Dn + col) =
            make_float2(o[nt][2] * inv1, o[nt][3] * inv1);
    }
}

// ---------------------------------------------------------------------------
// kernel_launch
// ---------------------------------------------------------------------------
extern "C" void kernel_launch(void* const* d_in, const int* in_sizes, int n_in,
                              void* d_out, int out_size) {
    (void)in_sizes; (void)n_in; (void)out_size;
    const float* query = (const float*)d_in[0];
    const float* key   = (const float*)d_in[1];
    const float* value = (const float*)d_in[2];
    const float* bias  = (const float*)d_in[3];
    const void*  mask  = d_in[4];
    const float* Wq = (const float*)d_in[5];
    const float* bq = (const float*)d_in[6];
    const float* Wk = (const float*)d_in[7];
    const float* bk = (const float*)d_in[8];
    const float* Wv = (const float*)d_in[9];
    const float* bv = (const float*)d_in[10];
    const float* Wo = (const float*)d_in[11];
    const float* bo = (const float*)d_in[12];
    float* out = (float*)d_out;

    cudaFuncSetAttribute(attn_kernel, cudaFuncAttributeMaxDynamicSharedMemorySize, SMEM_ATTN);
    cudaFuncSetAttribute(qkv_proj_kernel, cudaFuncAttributeMaxDynamicSharedMemorySize, SMEM_GEMM);
    cudaFuncSetAttribute(outproj_kernel, cudaFuncAttributeMaxDynamicSharedMemorySize, SMEM_GEMM);

    mask_prep_kernel<<<1, 256>>>(mask);
    bias_tr_kernel<<<dim3(Sn / 128, Sn, Bn), 256>>>(bias);
    qkv_proj_kernel<<<dim3(Dn / 128, (Bn * Sn) / 128, 3), 256, SMEM_GEMM>>>(
        query, key, value, Wq, Wk, Wv, bq, bk, bv);
    attn_kernel<<<dim3(Sn / 128, Hn, Bn), 256, SMEM_ATTN>>>();
    outproj_kernel<<<dim3(Dn / 128, (Bn * Sn) / 128, 1), 256, SMEM_GEMM>>>(Wo, bo, out);
}

// round 5
// speedup vs baseline: 1.0190x; 1.0190x over previous
#include <cuda_runtime.h>
#include <cuda_bf16.h>

// ---------------------------------------------------------------------------
// Problem constants
// ---------------------------------------------------------------------------
#define Bn  4
#define Sn  1024
#define Dn  1024
#define Hn  16
#define DKn 64

// ---------------------------------------------------------------------------
// Device scratch
// ---------------------------------------------------------------------------
__device__ float g_q[(size_t)Bn * Hn * Sn * DKn];      // [B,H,S,DK]
__device__ float g_k[(size_t)Bn * Hn * Sn * DKn];
__device__ float g_v[(size_t)Bn * Hn * Sn * DKn];
__device__ float g_biasT[(size_t)Bn * Hn * Sn * Sn];   // [B,H,S,S]
__device__ float g_ctx[(size_t)Bn * Sn * Dn];          // [B,S,D]
__device__ unsigned char g_mask[Bn * Sn];

// ---------------------------------------------------------------------------
// Helpers
// ---------------------------------------------------------------------------
__device__ __forceinline__ unsigned f2tf32(float x) {
    unsigned r;
    asm("cvt.rna.tf32.f32 %0, %1;" : "=r"(r) : "f"(x));
    return r;
}

__device__ __forceinline__ void mma_tf32(float c[4], const unsigned a[4], const unsigned b[2]) {
    asm volatile(
        "mma.sync.aligned.m16n8k8.row.col.f32.tf32.tf32.f32 "
        "{%0,%1,%2,%3},{%4,%5,%6,%7},{%8,%9},{%0,%1,%2,%3};\n"
        : "+f"(c[0]), "+f"(c[1]), "+f"(c[2]), "+f"(c[3])
        : "r"(a[0]), "r"(a[1]), "r"(a[2]), "r"(a[3]), "r"(b[0]), "r"(b[1]));
}

__device__ __forceinline__ float2 ldcs2(const float* p) {
    float2 r;
    asm volatile("ld.global.cs.v2.f32 {%0,%1}, [%2];" : "=f"(r.x), "=f"(r.y) : "l"(p));
    return r;
}

// ---------------------------------------------------------------------------
// Mask normalization
// ---------------------------------------------------------------------------
__global__ void mask_prep_kernel(const void* __restrict__ mraw) {
    __shared__ int flags[2];
    if (threadIdx.x < 2) flags[threadIdx.x] = 0;
    __syncthreads();
    const unsigned* w = (const unsigned*)mraw;
    for (int i = threadIdx.x; i < 1024; i += blockDim.x) {
        unsigned v = w[i];
        if (v > 1u) flags[0] = 1;
        if (v != 0u && v != 0x3F800000u) flags[1] = 1;
    }
    __syncthreads();
    int mode = flags[0] ? (flags[1] ? 0 : 2) : 1;
    for (int i = threadIdx.x; i < Bn * Sn; i += blockDim.x) {
        unsigned char v;
        if (mode == 1)      v = (((const int*)mraw)[i] != 0);
        else if (mode == 2) v = (((const float*)mraw)[i] != 0.f);
        else                v = (((const unsigned char*)mraw)[i] != 0);
        g_mask[i] = v;
    }
}

// ---------------------------------------------------------------------------
// Bias transpose [B,S,S,H] -> [B,H,S,S]
// ---------------------------------------------------------------------------
__global__ void bias_tr_kernel(const float* __restrict__ bias) {
    __shared__ float t[16][129];
    const int k0 = blockIdx.x * 128;
    const int q  = blockIdx.y;
    const int b  = blockIdx.z;
    const float* src = bias + ((size_t)(b * Sn + q) * Sn + k0) * Hn;
    for (int i = threadIdx.x; i < 2048; i += 256) {
        int kk = i >> 4, hh = i & 15;
        float v;
        asm volatile("ld.global.cs.f32 %0, [%1];" : "=f"(v) : "l"(src + i));
        t[hh][kk] = v;
    }
    __syncthreads();
    for (int i = threadIdx.x; i < 2048; i += 256) {
        int hh = i >> 7, kk = i & 127;
        float v = t[hh][kk];
        float* dst = &g_biasT[((size_t)(b * Hn + hh) * Sn + q) * Sn + k0 + kk];
        asm volatile("st.global.cs.f32 [%0], %1;" :: "l"(dst), "f"(v));
    }
}

// ---------------------------------------------------------------------------
// TN GEMM (single-buffered smem + register staging), paired-column layout
// (stride 40, 32-word rows) -> conflict-free LDS.64 fragment loads.
// ---------------------------------------------------------------------------
#define GS 40

template <int MODE>
__device__ __forceinline__ void gemm_tn_128(const float* __restrict__ A,
                                            const float* __restrict__ W,
                                            const float* __restrict__ bvec,
                                            float* __restrict__ out) {
    __shared__ unsigned sA[128 * GS];
    __shared__ unsigned sW[128 * GS];

    const int tid  = threadIdx.x;
    const int lane = tid & 31;
    const int warp = tid >> 5;
    const int j    = lane & 3;
    const int wm = (warp >> 2) * 64;
    const int wn = (warp & 3) * 32;
    const int m0 = blockIdx.y * 128;
    const int n0 = blockIdx.x * 128;

    float acc[4][4][4];
#pragma unroll
    for (int mt = 0; mt < 4; mt++)
#pragma unroll
        for (int nt = 0; nt < 4; nt++)
#pragma unroll
            for (int q = 0; q < 4; q++) acc[mt][nt][q] = 0.f;

    float4 ra[4], rw[4];
#pragma unroll
    for (int i = 0; i < 4; i++) {
        int task = i * 256 + tid;
        int row = task >> 3, c4 = task & 7;
        ra[i] = *(const float4*)(A + (size_t)(m0 + row) * Dn + c4 * 4);
        rw[i] = *(const float4*)(W + (size_t)(n0 + row) * Dn + c4 * 4);
    }

    for (int kt = 0; kt < 32; kt++) {
#pragma unroll
        for (int i = 0; i < 4; i++) {
            int task = i * 256 + tid;
            int row = task >> 3, c4 = task & 7;
            int base = row * GS + ((c4 >> 1) << 3) + (c4 & 1);
            sA[base + 0] = f2tf32(ra[i].x); sA[base + 2] = f2tf32(ra[i].y);
            sA[base + 4] = f2tf32(ra[i].z); sA[base + 6] = f2tf32(ra[i].w);
            sW[base + 0] = f2tf32(rw[i].x); sW[base + 2] = f2tf32(rw[i].y);
            sW[base + 4] = f2tf32(rw[i].z); sW[base + 6] = f2tf32(rw[i].w);
        }
        __syncthreads();

        if (kt < 31) {
            int kb = (kt + 1) * 32;
#pragma unroll
            for (int i = 0; i < 4; i++) {
                int task = i * 256 + tid;
                int row = task >> 3, c4 = task & 7;
                ra[i] = *(const float4*)(A + (size_t)(m0 + row) * Dn + kb + c4 * 4);
                rw[i] = *(const float4*)(W + (size_t)(n0 + row) * Dn + kb + c4 * 4);
            }
        }

#pragma unroll
        for (int ks = 0; ks < 4; ks++) {
            const int off = ks * 8 + 2 * j;
            unsigned afr[4][4];
#pragma unroll
            for (int mt = 0; mt < 4; mt++) {
                int r = wm + mt * 16 + (lane >> 2);
                uint2 u0 = *(const uint2*)&sA[r * GS + off];
                uint2 u1 = *(const uint2*)&sA[(r + 8) * GS + off];
                afr[mt][0] = u0.x; afr[mt][1] = u1.x;
                afr[mt][2] = u0.y; afr[mt][3] = u1.y;
            }
            unsigned bfr[4][2];
#pragma unroll
            for (int nt = 0; nt < 4; nt++) {
                int r = wn + nt * 8 + (lane >> 2);
                uint2 ub = *(const uint2*)&sW[r * GS + off];
                bfr[nt][0] = ub.x; bfr[nt][1] = ub.y;
            }
#pragma unroll
            for (int mt = 0; mt < 4; mt++)
#pragma unroll
                for (int nt = 0; nt < 4; nt++)
                    mma_tf32(acc[mt][nt], afr[mt], bfr[nt]);
        }
        __syncthreads();
    }

#pragma unroll
    for (int mt = 0; mt < 4; mt++) {
#pragma unroll
        for (int nt = 0; nt < 4; nt++) {
            int row = m0 + wm + mt * 16 + (lane >> 2);
            int col = n0 + wn + nt * 8 + (j << 1);
            float b0 = bvec[col], b1 = bvec[col + 1];
            float2 v0 = make_float2(acc[mt][nt][0] + b0, acc[mt][nt][1] + b1);
            float2 v1 = make_float2(acc[mt][nt][2] + b0, acc[mt][nt][3] + b1);
            if (MODE == 0) {
                *(float2*)(out + (size_t)row * Dn + col) = v0;
                *(float2*)(out + (size_t)(row + 8) * Dn + col) = v1;
            } else {
                int hh = col >> 6, dk = col & 63;
                int bb0 = row >> 10, s0 = row & 1023;
                int r8 = row + 8;
                int bb1 = r8 >> 10, s1 = r8 & 1023;
                *(float2*)(out + ((size_t)(bb0 * Hn + hh) * Sn + s0) * DKn + dk) = v0;
                *(float2*)(out + ((size_t)(bb1 * Hn + hh) * Sn + s1) * DKn + dk) = v1;
            }
        }
    }
}

__global__ void __launch_bounds__(256) qkv_proj_kernel(
    const float* __restrict__ Xq, const float* __restrict__ Xk, const float* __restrict__ Xv,
    const float* __restrict__ Wq, const float* __restrict__ Wk, const float* __restrict__ Wv,
    const float* __restrict__ bq, const float* __restrict__ bk, const float* __restrict__ bv) {
    int z = blockIdx.z;
    const float* A = (z == 0) ? Xq : (z == 1) ? Xk : Xv;
    const float* W = (z == 0) ? Wq : (z == 1) ? Wk : Wv;
    const float* bb = (z == 0) ? bq : (z == 1) ? bk : bv;
    float* out = (z == 0) ? g_q : (z == 1) ? g_k : g_v;
    gemm_tn_128<1>(A, W, bb, out);
}

__global__ void __launch_bounds__(256) outproj_kernel(
    const float* __restrict__ Wo, const float* __restrict__ bo, float* __restrict__ out) {
    gemm_tn_128<0>(g_ctx, Wo, bo, out);
}

// ---------------------------------------------------------------------------
// Flash attention v4: 64 q-rows, 128 threads, 3 CTAs/SM.
//  - sK / sP: paired-column layout, stride 72 (64-word rows + pad) -> LDS.64
//  - sV: plain layout stride 72, uint4 writes, conflict-free scalar reads
//  - Q fragments register-resident; bias loaded into mma accumulators
// ---------------------------------------------------------------------------
#define AS  72
#define AVS 72

__global__ void __launch_bounds__(128, 3) attn_kernel() {
    __shared__ unsigned sK[64 * AS];
    __shared__ unsigned sP[64 * AS];
    __shared__ unsigned sV[64 * AVS];
    __shared__ unsigned char smk[64];

    const int tid = threadIdx.x, lane = tid & 31, warp = tid >> 5;
    const int j = lane & 3;
    const int rq = warp * 16 + (lane >> 2);
    const int q0 = blockIdx.x * 64;
    const int h = blockIdx.y, b = blockIdx.z;

    const size_t headoff = (size_t)(b * Hn + h) * Sn * DKn;
    const float* Qg = g_q + headoff + (size_t)q0 * DKn;
    const float* Kg = g_k + headoff;
    const float* Vg = g_v + headoff;
    const float* Bg = g_biasT + ((size_t)(b * Hn + h) * Sn + q0) * Sn;
    const unsigned char* Mg = g_mask + b * Sn;

    // --- Stage Q into sP (paired layout), then fragments -> registers ---
#pragma unroll
    for (int i = 0; i < 8; i++) {
        int task = i * 128 + tid;
        int row = task >> 4, c4 = task & 15;
        float4 v = *(const float4*)(Qg + (size_t)row * DKn + c4 * 4);
        int base = row * AS + ((c4 >> 1) << 3) + (c4 & 1);
        sP[base + 0] = f2tf32(v.x); sP[base + 2] = f2tf32(v.y);
        sP[base + 4] = f2tf32(v.z); sP[base + 6] = f2tf32(v.w);
    }
    __syncthreads();

    unsigned qfr[8][4];
#pragma unroll
    for (int ks = 0; ks < 8; ks++) {
        int off = ks * 8 + 2 * j;
        uint2 u0 = *(const uint2*)&sP[rq * AS + off];
        uint2 u1 = *(const uint2*)&sP[(rq + 8) * AS + off];
        qfr[ks][0] = u0.x; qfr[ks][1] = u1.x; qfr[ks][2] = u0.y; qfr[ks][3] = u1.y;
    }
    __syncthreads();

    const int mq0 = Mg[q0 + rq];
    const int mq1 = Mg[q0 + rq + 8];

    float mrow0 = -1e30f, mrow1 = -1e30f, lrow0 = 0.f, lrow1 = 0.f;
    float o[8][4];
#pragma unroll
    for (int nt = 0; nt < 8; nt++)
#pragma unroll
        for (int q = 0; q < 4; q++) o[nt][q] = 0.f;

    // P-store slot: col = nt*8 + 2j -> word offset within 8-group
    const int poff = (j & 1) * 4 + (j >> 1);

    for (int kt = 0; kt < 16; kt++) {
        const int kv0 = kt * 64;

        // --- bias directly into accumulators (overlaps K/V staging latency) ---
        float s[8][4];
#pragma unroll
        for (int nt = 0; nt < 8; nt++) {
            int col = kv0 + nt * 8 + (j << 1);
            float2 t0 = ldcs2(Bg + (size_t)rq * Sn + col);
            float2 t1 = ldcs2(Bg + (size_t)(rq + 8) * Sn + col);
            s[nt][0] = t0.x; s[nt][1] = t0.y; s[nt][2] = t1.x; s[nt][3] = t1.y;
        }

        __syncthreads();  // previous PV done; sK/sV reusable
#pragma unroll
        for (int i = 0; i < 8; i++) {
            int task = i * 128 + tid;
            int row = task >> 4, c4 = task & 15;
            float4 kv = *(const float4*)(Kg + (size_t)(kv0 + row) * DKn + c4 * 4);
            int base = row * AS + ((c4 >> 1) << 3) + (c4 & 1);
            sK[base + 0] = f2tf32(kv.x); sK[base + 2] = f2tf32(kv.y);
            sK[base + 4] = f2tf32(kv.z); sK[base + 6] = f2tf32(kv.w);
            float4 vv = *(const float4*)(Vg + (size_t)(kv0 + row) * DKn + c4 * 4);
            *(uint4*)&sV[row * AVS + c4 * 4] =
                make_uint4(f2tf32(vv.x), f2tf32(vv.y), f2tf32(vv.z), f2tf32(vv.w));
        }
        if (tid < 64) smk[tid] = Mg[kv0 + tid];
        __syncthreads();

        // --- S = bias + Q K^T ---
#pragma unroll
        for (int ks = 0; ks < 8; ks++) {
            const int off = ks * 8 + 2 * j;
#pragma unroll
            for (int nt = 0; nt < 8; nt++) {
                uint2 ub = *(const uint2*)&sK[(nt * 8 + (lane >> 2)) * AS + off];
                unsigned bfr[2] = {ub.x, ub.y};
                mma_tf32(s[nt], qfr[ks], bfr);
            }
        }

        // --- scale + mask + online softmax ---
        float rmax0 = -1e30f, rmax1 = -1e30f;
#pragma unroll
        for (int nt = 0; nt < 8; nt++) {
            int col = nt * 8 + (j << 1);
            int k0ok = smk[col], k1ok = smk[col + 1];
            float v0 = (mq0 & k0ok) ? s[nt][0] * 0.125f : -1e9f;
            float v1 = (mq0 & k1ok) ? s[nt][1] * 0.125f : -1e9f;
            float v2 = (mq1 & k0ok) ? s[nt][2] * 0.125f : -1e9f;
            float v3 = (mq1 & k1ok) ? s[nt][3] * 0.125f : -1e9f;
            s[nt][0] = v0; s[nt][1] = v1; s[nt][2] = v2; s[nt][3] = v3;
            rmax0 = fmaxf(rmax0, fmaxf(v0, v1));
            rmax1 = fmaxf(rmax1, fmaxf(v2, v3));
        }
        rmax0 = fmaxf(rmax0, __shfl_xor_sync(0xffffffffu, rmax0, 1));
        rmax0 = fmaxf(rmax0, __shfl_xor_sync(0xffffffffu, rmax0, 2));
        rmax1 = fmaxf(rmax1, __shfl_xor_sync(0xffffffffu, rmax1, 1));
        rmax1 = fmaxf(rmax1, __shfl_xor_sync(0xffffffffu, rmax1, 2));

        float mnew0 = fmaxf(mrow0, rmax0), mnew1 = fmaxf(mrow1, rmax1);
        float alpha0 = __expf(mrow0 - mnew0), alpha1 = __expf(mrow1 - mnew1);
        mrow0 = mnew0; mrow1 = mnew1;

        float sum0 = 0.f, sum1 = 0.f;
#pragma unroll
        for (int nt = 0; nt < 8; nt++) {
            s[nt][0] = __expf(s[nt][0] - mnew0); sum0 += s[nt][0];
            s[nt][1] = __expf(s[nt][1] - mnew0); sum0 += s[nt][1];
            s[nt][2] = __expf(s[nt][2] - mnew1); sum1 += s[nt][2];
            s[nt][3] = __expf(s[nt][3] - mnew1); sum1 += s[nt][3];
        }
        sum0 += __shfl_xor_sync(0xffffffffu, sum0, 1);
        sum0 += __shfl_xor_sync(0xffffffffu, sum0, 2);
        sum1 += __shfl_xor_sync(0xffffffffu, sum1, 1);
        sum1 += __shfl_xor_sync(0xffffffffu, sum1, 2);
        lrow0 = lrow0 * alpha0 + sum0;
        lrow1 = lrow1 * alpha1 + sum1;

#pragma unroll
        for (int nt = 0; nt < 8; nt++) {
            o[nt][0] *= alpha0; o[nt][1] *= alpha0;
            o[nt][2] *= alpha1; o[nt][3] *= alpha1;
        }

        // --- P -> sP paired (rows warp-private: syncwarp suffices) ---
#pragma unroll
        for (int nt = 0; nt < 8; nt++) {
            int b0i = rq * AS + nt * 8 + poff;
            int b1i = (rq + 8) * AS + nt * 8 + poff;
            sP[b0i]     = f2tf32(s[nt][0]);
            sP[b0i + 2] = f2tf32(s[nt][1]);
            sP[b1i]     = f2tf32(s[nt][2]);
            sP[b1i + 2] = f2tf32(s[nt][3]);
        }
        __syncwarp();

        // --- O += P V ---
#pragma unroll
        for (int ks = 0; ks < 8; ks++) {
            const int kk = ks * 8;
            const int off = kk + 2 * j;
            uint2 u0 = *(const uint2*)&sP[rq * AS + off];
            uint2 u1 = *(const uint2*)&sP[(rq + 8) * AS + off];
            unsigned afr[4] = {u0.x, u1.x, u0.y, u1.y};
#pragma unroll
            for (int nt = 0; nt < 8; nt++) {
                int n = nt * 8 + (lane >> 2);
                unsigned bfr[2] = {sV[(kk + j) * AVS + n], sV[(kk + 4 + j) * AVS + n]};
                mma_tf32(o[nt], afr, bfr);
            }
        }
    }

    // --- epilogue ---
    float inv0 = 1.f / lrow0, inv1 = 1.f / lrow1;
    float* Cg = g_ctx + ((size_t)b * Sn + q0) * Dn + h * DKn;
#pragma unroll
    for (int nt = 0; nt < 8; nt++) {
        int col = nt * 8 + (j << 1);
        *(float2*)(Cg + (size_t)rq * Dn + col) =
            make_float2(o[nt][0] * inv0, o[nt][1] * inv0);
        *(float2*)(Cg + (size_t)(rq + 8) * Dn + col) =
            make_float2(o[nt][2] * inv1, o[nt][3] * inv1);
    }
}

// ---------------------------------------------------------------------------
// kernel_launch
// ---------------------------------------------------------------------------
extern "C" void kernel_launch(void* const* d_in, const int* in_sizes, int n_in,
                              void* d_out, int out_size) {
    (void)in_sizes; (void)n_in; (void)out_size;
    const float* query = (const float*)d_in[0];
    const float* key   = (const float*)d_in[1];
    const float* value = (const float*)d_in[2];
    const float* bias  = (const float*)d_in[3];
    const void*  mask  = d_in[4];
    const float* Wq = (const float*)d_in[5];
    const float* bq = (const float*)d_in[6];
    const float* Wk = (const float*)d_in[7];
    const float* bk = (const float*)d_in[8];
    const float* Wv = (const float*)d_in[9];
    const float* bv = (const float*)d_in[10];
    const float* Wo = (const float*)d_in[11];
    const float* bo = (const float*)d_in[12];
    float* out = (float*)d_out;

    mask_prep_kernel<<<1, 256>>>(mask);
    bias_tr_kernel<<<dim3(Sn / 128, Sn, Bn), 256>>>(bias);
    qkv_proj_kernel<<<dim3(Dn / 128, (Bn * Sn) / 128, 3), 256>>>(
        query, key, value, Wq, Wk, Wv, bq, bk, bv);
    attn_kernel<<<dim3(Sn / 64, Hn, Bn), 128>>>();
    outproj_kernel<<<dim3(Dn / 128, (Bn * Sn) / 128, 1), 256>>>(Wo, bo, out);
}

// round 6
// speedup vs baseline: 1.2322x; 1.2092x over previous
#include <cuda_runtime.h>
#include <cuda_bf16.h>

// ---------------------------------------------------------------------------
// Problem constants
// ---------------------------------------------------------------------------
#define Bn  4
#define Sn  1024
#define Dn  1024
#define Hn  16
#define DKn 64

// ---------------------------------------------------------------------------
// Device scratch
// ---------------------------------------------------------------------------
__device__ float g_q[(size_t)Bn * Hn * Sn * DKn];      // [B,H,S,DK]
__device__ float g_k[(size_t)Bn * Hn * Sn * DKn];
__device__ float g_v[(size_t)Bn * Hn * Sn * DKn];
__device__ float g_biasT[(size_t)Bn * Hn * Sn * Sn];   // [B,H,S,S]
__device__ float g_ctx[(size_t)Bn * Sn * Dn];          // [B,S,D]
__device__ unsigned char g_mask[Bn * Sn];

// ---------------------------------------------------------------------------
// Helpers
// ---------------------------------------------------------------------------
__device__ __forceinline__ unsigned f2tf32(float x) {
    unsigned r;
    asm("cvt.rna.tf32.f32 %0, %1;" : "=r"(r) : "f"(x));
    return r;
}

__device__ __forceinline__ void mma_tf32(float c[4], const unsigned a[4], const unsigned b[2]) {
    asm volatile(
        "mma.sync.aligned.m16n8k8.row.col.f32.tf32.tf32.f32 "
        "{%0,%1,%2,%3},{%4,%5,%6,%7},{%8,%9},{%0,%1,%2,%3};\n"
        : "+f"(c[0]), "+f"(c[1]), "+f"(c[2]), "+f"(c[3])
        : "r"(a[0]), "r"(a[1]), "r"(a[2]), "r"(a[3]), "r"(b[0]), "r"(b[1]));
}

__device__ __forceinline__ float2 ldcs2(const float* p) {
    float2 r;
    asm volatile("ld.global.cs.v2.f32 {%0,%1}, [%2];" : "=f"(r.x), "=f"(r.y) : "l"(p));
    return r;
}

// ---------------------------------------------------------------------------
// Mask normalization
// ---------------------------------------------------------------------------
__global__ void mask_prep_kernel(const void* __restrict__ mraw) {
    __shared__ int flags[2];
    if (threadIdx.x < 2) flags[threadIdx.x] = 0;
    __syncthreads();
    const unsigned* w = (const unsigned*)mraw;
    for (int i = threadIdx.x; i < 1024; i += blockDim.x) {
        unsigned v = w[i];
        if (v > 1u) flags[0] = 1;
        if (v != 0u && v != 0x3F800000u) flags[1] = 1;
    }
    __syncthreads();
    int mode = flags[0] ? (flags[1] ? 0 : 2) : 1;
    for (int i = threadIdx.x; i < Bn * Sn; i += blockDim.x) {
        unsigned char v;
        if (mode == 1)      v = (((const int*)mraw)[i] != 0);
        else if (mode == 2) v = (((const float*)mraw)[i] != 0.f);
        else                v = (((const unsigned char*)mraw)[i] != 0);
        g_mask[i] = v;
    }
}

// ---------------------------------------------------------------------------
// Bias transpose [B,S,S,H] -> [B,H,S,S]
// ---------------------------------------------------------------------------
__global__ void bias_tr_kernel(const float* __restrict__ bias) {
    __shared__ float t[16][129];
    const int k0 = blockIdx.x * 128;
    const int q  = blockIdx.y;
    const int b  = blockIdx.z;
    const float* src = bias + ((size_t)(b * Sn + q) * Sn + k0) * Hn;
    for (int i = threadIdx.x; i < 2048; i += 256) {
        int kk = i >> 4, hh = i & 15;
        float v;
        asm volatile("ld.global.cs.f32 %0, [%1];" : "=f"(v) : "l"(src + i));
        t[hh][kk] = v;
    }
    __syncthreads();
    for (int i = threadIdx.x; i < 2048; i += 256) {
        int hh = i >> 7, kk = i & 127;
        float v = t[hh][kk];
        float* dst = &g_biasT[((size_t)(b * Hn + hh) * Sn + q) * Sn + k0 + kk];
        asm volatile("st.global.cs.f32 [%0], %1;" :: "l"(dst), "f"(v));
    }
}

// ---------------------------------------------------------------------------
// TN GEMM (R1 exact): C[M,N] = A[M,1024] * W[N,1024]^T + bias[n]
// 128x128x32 CTA tile, 256 threads, single-buffered smem, register staging,
// consecutive-word smem stores (merge to STS.128).
// ---------------------------------------------------------------------------
template <int MODE>
__device__ __forceinline__ void gemm_tn_128(const float* __restrict__ A,
                                            const float* __restrict__ W,
                                            const float* __restrict__ bvec,
                                            float* __restrict__ out) {
    __shared__ unsigned sA[128 * 36];
    __shared__ unsigned sW[128 * 36];

    const int tid  = threadIdx.x;
    const int lane = tid & 31;
    const int warp = tid >> 5;
    const int wm = (warp >> 2) * 64;   // 0 / 64
    const int wn = (warp & 3) * 32;    // 0 / 32 / 64 / 96
    const int m0 = blockIdx.y * 128;
    const int n0 = blockIdx.x * 128;

    float acc[4][4][4];
#pragma unroll
    for (int mt = 0; mt < 4; mt++)
#pragma unroll
        for (int nt = 0; nt < 4; nt++)
#pragma unroll
            for (int j = 0; j < 4; j++) acc[mt][nt][j] = 0.f;

    float4 ra[4], rw[4];
#pragma unroll
    for (int i = 0; i < 4; i++) {
        int task = i * 256 + tid;
        int row = task >> 3, c4 = task & 7;
        ra[i] = *(const float4*)(A + (size_t)(m0 + row) * Dn + c4 * 4);
        rw[i] = *(const float4*)(W + (size_t)(n0 + row) * Dn + c4 * 4);
    }

    for (int kt = 0; kt < 32; kt++) {
#pragma unroll
        for (int i = 0; i < 4; i++) {
            int task = i * 256 + tid;
            int row = task >> 3, c4 = task & 7;
            unsigned* pA = &sA[row * 36 + c4 * 4];
            pA[0] = f2tf32(ra[i].x); pA[1] = f2tf32(ra[i].y);
            pA[2] = f2tf32(ra[i].z); pA[3] = f2tf32(ra[i].w);
            unsigned* pW = &sW[row * 36 + c4 * 4];
            pW[0] = f2tf32(rw[i].x); pW[1] = f2tf32(rw[i].y);
            pW[2] = f2tf32(rw[i].z); pW[3] = f2tf32(rw[i].w);
        }
        __syncthreads();

        if (kt < 31) {
            int kb = (kt + 1) * 32;
#pragma unroll
            for (int i = 0; i < 4; i++) {
                int task = i * 256 + tid;
                int row = task >> 3, c4 = task & 7;
                ra[i] = *(const float4*)(A + (size_t)(m0 + row) * Dn + kb + c4 * 4);
                rw[i] = *(const float4*)(W + (size_t)(n0 + row) * Dn + kb + c4 * 4);
            }
        }

#pragma unroll
        for (int ks = 0; ks < 4; ks++) {
            const int kk = ks * 8;
            unsigned afr[4][4];
#pragma unroll
            for (int mt = 0; mt < 4; mt++) {
                int r = wm + mt * 16 + (lane >> 2);
                int c = kk + (lane & 3);
                afr[mt][0] = sA[r * 36 + c];
                afr[mt][1] = sA[(r + 8) * 36 + c];
                afr[mt][2] = sA[r * 36 + c + 4];
                afr[mt][3] = sA[(r + 8) * 36 + c + 4];
            }
            unsigned bfr[4][2];
#pragma unroll
            for (int nt = 0; nt < 4; nt++) {
                int r = wn + nt * 8 + (lane >> 2);
                int c = kk + (lane & 3);
                bfr[nt][0] = sW[r * 36 + c];
                bfr[nt][1] = sW[r * 36 + c + 4];
            }
#pragma unroll
            for (int mt = 0; mt < 4; mt++)
#pragma unroll
                for (int nt = 0; nt < 4; nt++)
                    mma_tf32(acc[mt][nt], afr[mt], bfr[nt]);
        }
        __syncthreads();
    }

#pragma unroll
    for (int mt = 0; mt < 4; mt++) {
#pragma unroll
        for (int nt = 0; nt < 4; nt++) {
            int row = m0 + wm + mt * 16 + (lane >> 2);
            int col = n0 + wn + nt * 8 + ((lane & 3) << 1);
            float b0 = bvec[col], b1 = bvec[col + 1];
            float2 v0 = make_float2(acc[mt][nt][0] + b0, acc[mt][nt][1] + b1);
            float2 v1 = make_float2(acc[mt][nt][2] + b0, acc[mt][nt][3] + b1);
            if (MODE == 0) {
                *(float2*)(out + (size_t)row * Dn + col) = v0;
                *(float2*)(out + (size_t)(row + 8) * Dn + col) = v1;
            } else {
                int hh = col >> 6, dk = col & 63;
                int bb0 = row >> 10, s0 = row & 1023;
                int r8 = row + 8;
                int bb1 = r8 >> 10, s1 = r8 & 1023;
                *(float2*)(out + ((size_t)(bb0 * Hn + hh) * Sn + s0) * DKn + dk) = v0;
                *(float2*)(out + ((size_t)(bb1 * Hn + hh) * Sn + s1) * DKn + dk) = v1;
            }
        }
    }
}

__global__ void __launch_bounds__(256) qkv_proj_kernel(
    const float* __restrict__ Xq, const float* __restrict__ Xk, const float* __restrict__ Xv,
    const float* __restrict__ Wq, const float* __restrict__ Wk, const float* __restrict__ Wv,
    const float* __restrict__ bq, const float* __restrict__ bk, const float* __restrict__ bv) {
    int z = blockIdx.z;
    const float* A = (z == 0) ? Xq : (z == 1) ? Xk : Xv;
    const float* W = (z == 0) ? Wq : (z == 1) ? Wk : Wv;
    const float* bb = (z == 0) ? bq : (z == 1) ? bk : bv;
    float* out = (z == 0) ? g_q : (z == 1) ? g_k : g_v;
    gemm_tn_128<1>(A, W, bb, out);
}

__global__ void __launch_bounds__(256) outproj_kernel(
    const float* __restrict__ Wo, const float* __restrict__ bo, float* __restrict__ out) {
    gemm_tn_128<0>(g_ctx, Wo, bo, out);
}

// ---------------------------------------------------------------------------
// Flash attention (R1 structure, 64 q-rows, 128 threads) with bias
// double-buffering: tile kt+1's bias is prefetched at the top of tile kt,
// so the QK mma never waits on DRAM. s starts as the bias (register copy).
// ---------------------------------------------------------------------------
#define SQS 68   // stride (floats) for sQ / sKP
#define SVS 72   // stride for sV

__global__ void __launch_bounds__(128) attn_kernel() {
    __shared__ unsigned sQ[64 * SQS];
    __shared__ unsigned sKP[64 * SQS];   // K tile, reused as P tile
    __shared__ unsigned sV[64 * SVS];
    __shared__ unsigned char smk[64];

    const int qt = blockIdx.x, h = blockIdx.y, b = blockIdx.z;
    const int q0 = qt * 64;
    const int tid = threadIdx.x, lane = tid & 31, warp = tid >> 5;
    const int rq = warp * 16 + (lane >> 2);

    const size_t headoff = (size_t)(b * Hn + h) * Sn * DKn;
    const float* Qg = g_q + headoff + (size_t)q0 * DKn;
    const float* Kg = g_k + headoff;
    const float* Vg = g_v + headoff;
    const float* Bg = g_biasT + ((size_t)(b * Hn + h) * Sn + q0) * Sn;
    const unsigned char* Mg = g_mask + b * Sn;

    // Load Q tile (tf32)
#pragma unroll
    for (int i = 0; i < 8; i++) {
        int task = i * 128 + tid;
        int row = task >> 4, c4 = task & 15;
        float4 v = *(const float4*)(Qg + (size_t)row * DKn + c4 * 4);
        uint4 t = make_uint4(f2tf32(v.x), f2tf32(v.y), f2tf32(v.z), f2tf32(v.w));
        *(uint4*)&sQ[row * SQS + c4 * 4] = t;
    }

    const int mq0 = Mg[q0 + rq];
    const int mq1 = Mg[q0 + rq + 8];

    float mrow0 = -1e30f, mrow1 = -1e30f, lrow0 = 0.f, lrow1 = 0.f;
    float o[8][4];
#pragma unroll
    for (int nt = 0; nt < 8; nt++)
#pragma unroll
        for (int j = 0; j < 4; j++) o[nt][j] = 0.f;

    // --- bias prefetch for tile 0 (registers, streaming loads) ---
    float2 nb0[8], nb1[8];
#pragma unroll
    for (int nt = 0; nt < 8; nt++) {
        int col = nt * 8 + ((lane & 3) << 1);
        nb0[nt] = ldcs2(Bg + (size_t)rq * Sn + col);
        nb1[nt] = ldcs2(Bg + (size_t)(rq + 8) * Sn + col);
    }

    for (int kt = 0; kt < 16; kt++) {
        const int kv0 = kt * 64;

        // Consume prefetched bias into accumulators (register copy — no DRAM
        // dependency on the mma chain), then immediately prefetch next tile.
        float s[8][4];
#pragma unroll
        for (int nt = 0; nt < 8; nt++) {
            s[nt][0] = nb0[nt].x; s[nt][1] = nb0[nt].y;
            s[nt][2] = nb1[nt].x; s[nt][3] = nb1[nt].y;
        }
        if (kt < 15) {
            const int ncol0 = kv0 + 64;
#pragma unroll
            for (int nt = 0; nt < 8; nt++) {
                int col = ncol0 + nt * 8 + ((lane & 3) << 1);
                nb0[nt] = ldcs2(Bg + (size_t)rq * Sn + col);
                nb1[nt] = ldcs2(Bg + (size_t)(rq + 8) * Sn + col);
            }
        }

        __syncthreads();  // sKP / sV free for reuse

        // Load K and V tiles (tf32), uint4 stores (STS.128)
#pragma unroll
        for (int i = 0; i < 8; i++) {
            int task = i * 128 + tid;
            int row = task >> 4, c4 = task & 15;
            float4 kv = *(const float4*)(Kg + (size_t)(kv0 + row) * DKn + c4 * 4);
            *(uint4*)&sKP[row * SQS + c4 * 4] =
                make_uint4(f2tf32(kv.x), f2tf32(kv.y), f2tf32(kv.z), f2tf32(kv.w));
            float4 vv = *(const float4*)(Vg + (size_t)(kv0 + row) * DKn + c4 * 4);
            *(uint4*)&sV[row * SVS + c4 * 4] =
                make_uint4(f2tf32(vv.x), f2tf32(vv.y), f2tf32(vv.z), f2tf32(vv.w));
        }
        if (tid < 64) smk[tid] = Mg[kv0 + tid];
        __syncthreads();

        // S = bias + Q K^T
#pragma unroll
        for (int ks = 0; ks < 8; ks++) {
            const int kk = ks * 8;
            unsigned afr[4];
            {
                int c = kk + (lane & 3);
                afr[0] = sQ[rq * SQS + c];
                afr[1] = sQ[(rq + 8) * SQS + c];
                afr[2] = sQ[rq * SQS + c + 4];
                afr[3] = sQ[(rq + 8) * SQS + c + 4];
            }
#pragma unroll
            for (int nt = 0; nt < 8; nt++) {
                unsigned bfr[2];
                int r = nt * 8 + (lane >> 2);
                int c = kk + (lane & 3);
                bfr[0] = sKP[r * SQS + c];
                bfr[1] = sKP[r * SQS + c + 4];
                mma_tf32(s[nt], afr, bfr);
            }
        }

        // scale + mask + online softmax
        float rmax0 = -1e30f, rmax1 = -1e30f;
#pragma unroll
        for (int nt = 0; nt < 8; nt++) {
            int col = nt * 8 + ((lane & 3) << 1);
            int k0ok = smk[col], k1ok = smk[col + 1];
            float v0 = (mq0 & k0ok) ? s[nt][0] * 0.125f : -1e9f;
            float v1 = (mq0 & k1ok) ? s[nt][1] * 0.125f : -1e9f;
            float v2 = (mq1 & k0ok) ? s[nt][2] * 0.125f : -1e9f;
            float v3 = (mq1 & k1ok) ? s[nt][3] * 0.125f : -1e9f;
            s[nt][0] = v0; s[nt][1] = v1; s[nt][2] = v2; s[nt][3] = v3;
            rmax0 = fmaxf(rmax0, fmaxf(v0, v1));
            rmax1 = fmaxf(rmax1, fmaxf(v2, v3));
        }
        rmax0 = fmaxf(rmax0, __shfl_xor_sync(0xffffffffu, rmax0, 1));
        rmax0 = fmaxf(rmax0, __shfl_xor_sync(0xffffffffu, rmax0, 2));
        rmax1 = fmaxf(rmax1, __shfl_xor_sync(0xffffffffu, rmax1, 1));
        rmax1 = fmaxf(rmax1, __shfl_xor_sync(0xffffffffu, rmax1, 2));

        float mnew0 = fmaxf(mrow0, rmax0), mnew1 = fmaxf(mrow1, rmax1);
        float alpha0 = __expf(mrow0 - mnew0), alpha1 = __expf(mrow1 - mnew1);
        mrow0 = mnew0; mrow1 = mnew1;

        float sum0 = 0.f, sum1 = 0.f;
#pragma unroll
        for (int nt = 0; nt < 8; nt++) {
            s[nt][0] = __expf(s[nt][0] - mnew0); sum0 += s[nt][0];
            s[nt][1] = __expf(s[nt][1] - mnew0); sum0 += s[nt][1];
            s[nt][2] = __expf(s[nt][2] - mnew1); sum1 += s[nt][2];
            s[nt][3] = __expf(s[nt][3] - mnew1); sum1 += s[nt][3];
        }
        sum0 += __shfl_xor_sync(0xffffffffu, sum0, 1);
        sum0 += __shfl_xor_sync(0xffffffffu, sum0, 2);
        sum1 += __shfl_xor_sync(0xffffffffu, sum1, 1);
        sum1 += __shfl_xor_sync(0xffffffffu, sum1, 2);
        lrow0 = lrow0 * alpha0 + sum0;
        lrow1 = lrow1 * alpha1 + sum1;

#pragma unroll
        for (int nt = 0; nt < 8; nt++) {
            o[nt][0] *= alpha0; o[nt][1] *= alpha0;
            o[nt][2] *= alpha1; o[nt][3] *= alpha1;
        }

        __syncthreads();  // all warps done reading sKP (K) -> overwrite with P
#pragma unroll
        for (int nt = 0; nt < 8; nt++) {
            int col = nt * 8 + ((lane & 3) << 1);
            *(uint2*)&sKP[rq * SQS + col] =
                make_uint2(f2tf32(s[nt][0]), f2tf32(s[nt][1]));
            *(uint2*)&sKP[(rq + 8) * SQS + col] =
                make_uint2(f2tf32(s[nt][2]), f2tf32(s[nt][3]));
        }
        __syncthreads();

        // O += P V
#pragma unroll
        for (int ks = 0; ks < 8; ks++) {
            const int kk = ks * 8;
            unsigned afr[4];
            {
                int c = kk + (lane & 3);
                afr[0] = sKP[rq * SQS + c];
                afr[1] = sKP[(rq + 8) * SQS + c];
                afr[2] = sKP[rq * SQS + c + 4];
                afr[3] = sKP[(rq + 8) * SQS + c + 4];
            }
#pragma unroll
            for (int nt = 0; nt < 8; nt++) {
                unsigned bfr[2];
                int n = nt * 8 + (lane >> 2);
                bfr[0] = sV[(kk + (lane & 3)) * SVS + n];
                bfr[1] = sV[(kk + 4 + (lane & 3)) * SVS + n];
                mma_tf32(o[nt], afr, bfr);
            }
        }
    }

    // Epilogue
    float inv0 = 1.f / lrow0, inv1 = 1.f / lrow1;
    float* Cg = g_ctx + ((size_t)b * Sn + q0) * Dn + h * DKn;
#pragma unroll
    for (int nt = 0; nt < 8; nt++) {
        int col = nt * 8 + ((lane & 3) << 1);
        *(float2*)(Cg + (size_t)rq * Dn + col) =
            make_float2(o[nt][0] * inv0, o[nt][1] * inv0);
        *(float2*)(Cg + (size_t)(rq + 8) * Dn + col) =
            make_float2(o[nt][2] * inv1, o[nt][3] * inv1);
    }
}

// ---------------------------------------------------------------------------
// kernel_launch
// ---------------------------------------------------------------------------
extern "C" void kernel_launch(void* const* d_in, const int* in_sizes, int n_in,
                              void* d_out, int out_size) {
    (void)in_sizes; (void)n_in; (void)out_size;
    const float* query = (const float*)d_in[0];
    const float* key   = (const float*)d_in[1];
    const float* value = (const float*)d_in[2];
    const float* bias  = (const float*)d_in[3];
    const void*  mask  = d_in[4];
    const float* Wq = (const float*)d_in[5];
    const float* bq = (const float*)d_in[6];
    const float* Wk = (const float*)d_in[7];
    const float* bk = (const float*)d_in[8];
    const float* Wv = (const float*)d_in[9];
    const float* bv = (const float*)d_in[10];
    const float* Wo = (const float*)d_in[11];
    const float* bo = (const float*)d_in[12];
    float* out = (float*)d_out;

    mask_prep_kernel<<<1, 256>>>(mask);
    bias_tr_kernel<<<dim3(Sn / 128, Sn, Bn), 256>>>(bias);
    qkv_proj_kernel<<<dim3(Dn / 128, (Bn * Sn) / 128, 3), 256>>>(
        query, key, value, Wq, Wk, Wv, bq, bk, bv);
    attn_kernel<<<dim3(Sn / 64, Hn, Bn), 128>>>();
    outproj_kernel<<<dim3(Dn / 128, (Bn * Sn) / 128, 1), 256>>>(Wo, bo, out);
}

// round 8
// speedup vs baseline: 1.6219x; 1.3163x over previous
#include <cuda_runtime.h>
#include <cuda_fp16.h>

// ---------------------------------------------------------------------------
// Problem constants
// ---------------------------------------------------------------------------
#define Bn  4
#define Sn  1024
#define Dn  1024
#define Hn  16
#define DKn 64

// ---------------------------------------------------------------------------
// Device scratch (q/k/v stored fp16; ctx fp32)
// ---------------------------------------------------------------------------
__device__ __half g_q[(size_t)Bn * Hn * Sn * DKn];     // [B,H,S,DK]
__device__ __half g_k[(size_t)Bn * Hn * Sn * DKn];
__device__ __half g_v[(size_t)Bn * Hn * Sn * DKn];
__device__ float  g_biasT[(size_t)Bn * Hn * Sn * Sn];  // [B,H,S,S]
__device__ float  g_ctx[(size_t)Bn * Sn * Dn];         // [B,S,D]
__device__ unsigned char g_mask[Bn * Sn];

// ---------------------------------------------------------------------------
// Helpers
// ---------------------------------------------------------------------------
__device__ __forceinline__ unsigned h2u(__half2 h) {
    return *reinterpret_cast<unsigned*>(&h);
}

__device__ __forceinline__ unsigned smaddr(const void* p) {
    return (unsigned)__cvta_generic_to_shared(p);
}

__device__ __forceinline__ void ldsm4(unsigned& r0, unsigned& r1, unsigned& r2,
                                      unsigned& r3, unsigned addr) {
    asm volatile("ldmatrix.sync.aligned.m8n8.x4.shared.b16 {%0,%1,%2,%3}, [%4];"
                 : "=r"(r0), "=r"(r1), "=r"(r2), "=r"(r3) : "r"(addr));
}

__device__ __forceinline__ void ldsm4t(unsigned& r0, unsigned& r1, unsigned& r2,
                                       unsigned& r3, unsigned addr) {
    asm volatile("ldmatrix.sync.aligned.m8n8.x4.trans.shared.b16 {%0,%1,%2,%3}, [%4];"
                 : "=r"(r0), "=r"(r1), "=r"(r2), "=r"(r3) : "r"(addr));
}

__device__ __forceinline__ void mma_f16(float c[4], const unsigned a[4],
                                        unsigned b0, unsigned b1) {
    asm volatile(
        "mma.sync.aligned.m16n8k16.row.col.f32.f16.f16.f32 "
        "{%0,%1,%2,%3},{%4,%5,%6,%7},{%8,%9},{%0,%1,%2,%3};\n"
        : "+f"(c[0]), "+f"(c[1]), "+f"(c[2]), "+f"(c[3])
        : "r"(a[0]), "r"(a[1]), "r"(a[2]), "r"(a[3]), "r"(b0), "r"(b1));
}

__device__ __forceinline__ float2 ldcs2(const float* p) {
    float2 r;
    asm volatile("ld.global.cs.v2.f32 {%0,%1}, [%2];" : "=f"(r.x), "=f"(r.y) : "l"(p));
    return r;
}

// ---------------------------------------------------------------------------
// Mask normalization
// ---------------------------------------------------------------------------
__global__ void mask_prep_kernel(const void* __restrict__ mraw) {
    __shared__ int flags[2];
    if (threadIdx.x < 2) flags[threadIdx.x] = 0;
    __syncthreads();
    const unsigned* w = (const unsigned*)mraw;
    for (int i = threadIdx.x; i < 1024; i += blockDim.x) {
        unsigned v = w[i];
        if (v > 1u) flags[0] = 1;
        if (v != 0u && v != 0x3F800000u) flags[1] = 1;
    }
    __syncthreads();
    int mode = flags[0] ? (flags[1] ? 0 : 2) : 1;
    for (int i = threadIdx.x; i < Bn * Sn; i += blockDim.x) {
        unsigned char v;
        if (mode == 1)      v = (((const int*)mraw)[i] != 0);
        else if (mode == 2) v = (((const float*)mraw)[i] != 0.f);
        else                v = (((const unsigned char*)mraw)[i] != 0);
        g_mask[i] = v;
    }
}

// ---------------------------------------------------------------------------
// Bias transpose [B,S,S,H] -> [B,H,S,S]
// ---------------------------------------------------------------------------
__global__ void bias_tr_kernel(const float* __restrict__ bias) {
    __shared__ float t[16][129];
    const int k0 = blockIdx.x * 128;
    const int q  = blockIdx.y;
    const int b  = blockIdx.z;
    const float* src = bias + ((size_t)(b * Sn + q) * Sn + k0) * Hn;
    for (int i = threadIdx.x; i < 2048; i += 256) {
        int kk = i >> 4, hh = i & 15;
        float v;
        asm volatile("ld.global.cs.f32 %0, [%1];" : "=f"(v) : "l"(src + i));
        t[hh][kk] = v;
    }
    __syncthreads();
    for (int i = threadIdx.x; i < 2048; i += 256) {
        int hh = i >> 7, kk = i & 127;
        float v = t[hh][kk];
        float* dst = &g_biasT[((size_t)(b * Hn + hh) * Sn + q) * Sn + k0 + kk];
        asm volatile("st.global.cs.f32 [%0], %1;" :: "l"(dst), "f"(v));
    }
}

// ---------------------------------------------------------------------------
// TN GEMM fp16: C[M,N] = A[M,1024] * W[N,1024]^T + bias[n]
// 128x128x32 tile, 256 threads, 8 warps (2m x 4n), single-buffered smem,
// register staging, ldmatrix fragment loads, m16n8k16 f16 mma (fp32 accum).
// ---------------------------------------------------------------------------
#define GSH 40   // smem stride in halves (80B: ldmatrix conflict-free)

template <int MODE>
__device__ __forceinline__ void gemm_f16(const float* __restrict__ A,
                                         const float* __restrict__ W,
                                         const float* __restrict__ bvec,
                                         void* __restrict__ outv) {
    __shared__ __half sA[128 * GSH];
    __shared__ __half sW[128 * GSH];

    const int tid  = threadIdx.x;
    const int lane = tid & 31;
    const int warp = tid >> 5;
    const int wm = (warp >> 2) * 64;
    const int wn = (warp & 3) * 32;
    const int m0 = blockIdx.y * 128;
    const int n0 = blockIdx.x * 128;

    float acc[4][4][4];
#pragma unroll
    for (int mt = 0; mt < 4; mt++)
#pragma unroll
        for (int nt = 0; nt < 4; nt++)
#pragma unroll
            for (int q = 0; q < 4; q++) acc[mt][nt][q] = 0.f;

    float4 ra[4], rw[4];
#pragma unroll
    for (int i = 0; i < 4; i++) {
        int task = i * 256 + tid;
        int row = task >> 3, c4 = task & 7;
        ra[i] = *(const float4*)(A + (size_t)(m0 + row) * Dn + c4 * 4);
        rw[i] = *(const float4*)(W + (size_t)(n0 + row) * Dn + c4 * 4);
    }

    for (int kt = 0; kt < 32; kt++) {
#pragma unroll
        for (int i = 0; i < 4; i++) {
            int task = i * 256 + tid;
            int row = task >> 3, c4 = task & 7;
            *(uint2*)&sA[row * GSH + c4 * 4] =
                make_uint2(h2u(__floats2half2_rn(ra[i].x, ra[i].y)),
                           h2u(__floats2half2_rn(ra[i].z, ra[i].w)));
            *(uint2*)&sW[row * GSH + c4 * 4] =
                make_uint2(h2u(__floats2half2_rn(rw[i].x, rw[i].y)),
                           h2u(__floats2half2_rn(rw[i].z, rw[i].w)));
        }
        __syncthreads();

        if (kt < 31) {
            int kb = (kt + 1) * 32;
#pragma unroll
            for (int i = 0; i < 4; i++) {
                int task = i * 256 + tid;
                int row = task >> 3, c4 = task & 7;
                ra[i] = *(const float4*)(A + (size_t)(m0 + row) * Dn + kb + c4 * 4);
                rw[i] = *(const float4*)(W + (size_t)(n0 + row) * Dn + kb + c4 * 4);
            }
        }

#pragma unroll
        for (int ks = 0; ks < 2; ks++) {
            const int koff = ks * 16 + ((lane >> 4) << 3);
            unsigned afr[4][4];
#pragma unroll
            for (int mt = 0; mt < 4; mt++)
                ldsm4(afr[mt][0], afr[mt][1], afr[mt][2], afr[mt][3],
                      smaddr(&sA[(wm + mt * 16 + (lane & 15)) * GSH + koff]));
            unsigned bfr[4][2];
#pragma unroll
            for (int ntp = 0; ntp < 2; ntp++) {
                unsigned t0, t1, t2, t3;
                ldsm4(t0, t1, t2, t3,
                      smaddr(&sW[(wn + ntp * 16 + (lane & 7) + (((lane >> 4) & 1) << 3)) * GSH +
                                 ks * 16 + (((lane >> 3) & 1) << 3)]));
                bfr[2 * ntp][0] = t0; bfr[2 * ntp][1] = t1;
                bfr[2 * ntp + 1][0] = t2; bfr[2 * ntp + 1][1] = t3;
            }
#pragma unroll
            for (int mt = 0; mt < 4; mt++)
#pragma unroll
                for (int nt = 0; nt < 4; nt++)
                    mma_f16(acc[mt][nt], afr[mt], bfr[nt][0], bfr[nt][1]);
        }
        __syncthreads();
    }

#pragma unroll
    for (int mt = 0; mt < 4; mt++) {
#pragma unroll
        for (int nt = 0; nt < 4; nt++) {
            int row = m0 + wm + mt * 16 + (lane >> 2);
            int col = n0 + wn + nt * 8 + ((lane & 3) << 1);
            float b0 = bvec[col], b1 = bvec[col + 1];
            float v00 = acc[mt][nt][0] + b0, v01 = acc[mt][nt][1] + b1;
            float v10 = acc[mt][nt][2] + b0, v11 = acc[mt][nt][3] + b1;
            if (MODE == 0) {
                float* out = (float*)outv;
                *(float2*)(out + (size_t)row * Dn + col) = make_float2(v00, v01);
                *(float2*)(out + (size_t)(row + 8) * Dn + col) = make_float2(v10, v11);
            } else {
                __half* out = (__half*)outv;
                int hh = col >> 6, dk = col & 63;
                int bb0 = row >> 10, s0 = row & 1023;
                int r8 = row + 8;
                int bb1 = r8 >> 10, s1 = r8 & 1023;
                *(__half2*)(out + ((size_t)(bb0 * Hn + hh) * Sn + s0) * DKn + dk) =
                    __floats2half2_rn(v00, v01);
                *(__half2*)(out + ((size_t)(bb1 * Hn + hh) * Sn + s1) * DKn + dk) =
                    __floats2half2_rn(v10, v11);
            }
        }
    }
}

__global__ void __launch_bounds__(256) qkv_proj_kernel(
    const float* __restrict__ Xq, const float* __restrict__ Xk, const float* __restrict__ Xv,
    const float* __restrict__ Wq, const float* __restrict__ Wk, const float* __restrict__ Wv,
    const float* __restrict__ bq, const float* __restrict__ bk, const float* __restrict__ bv) {
    int z = blockIdx.z;
    const float* A = (z == 0) ? Xq : (z == 1) ? Xk : Xv;
    const float* W = (z == 0) ? Wq : (z == 1) ? Wk : Wv;
    const float* bb = (z == 0) ? bq : (z == 1) ? bk : bv;
    __half* out = (z == 0) ? g_q : (z == 1) ? g_k : g_v;
    gemm_f16<1>(A, W, bb, out);
}

__global__ void __launch_bounds__(256) outproj_kernel(
    const float* __restrict__ Wo, const float* __restrict__ bo, float* __restrict__ out) {
    gemm_f16<0>(g_ctx, Wo, bo, out);
}

// ---------------------------------------------------------------------------
// Flash attention fp16: 64 q-rows, 128 threads (4 warps), R1 structure.
// ldmatrix fragments: sQ/sKP non-trans, sV trans (PV B from row-major V).
// ---------------------------------------------------------------------------
#define ASH 72   // smem stride in halves (144B: ldmatrix conflict-free)

__global__ void __launch_bounds__(128) attn_kernel() {
    __shared__ __half sQ[64 * ASH];
    __shared__ __half sKP[64 * ASH];   // K tile, reused as P tile
    __shared__ __half sV[64 * ASH];
    __shared__ unsigned char smk[64];

    const int qt = blockIdx.x, h = blockIdx.y, b = blockIdx.z;
    const int q0 = qt * 64;
    const int tid = threadIdx.x, lane = tid & 31, warp = tid >> 5;
    const int rq = warp * 16 + (lane >> 2);

    const size_t headoff = (size_t)(b * Hn + h) * Sn * DKn;
    const __half* Qg = g_q + headoff + (size_t)q0 * DKn;
    const __half* Kg = g_k + headoff;
    const __half* Vg = g_v + headoff;
    const float* Bg = g_biasT + ((size_t)(b * Hn + h) * Sn + q0) * Sn;
    const unsigned char* Mg = g_mask + b * Sn;

    // Load Q tile (fp16, straight copy)
#pragma unroll
    for (int i = 0; i < 4; i++) {
        int task = i * 128 + tid;
        int row = task >> 3, c4 = task & 7;
        *(uint4*)&sQ[row * ASH + c4 * 8] = *(const uint4*)(Qg + (size_t)row * DKn + c4 * 8);
    }

    const int mq0 = Mg[q0 + rq];
    const int mq1 = Mg[q0 + rq + 8];

    float mrow0 = -1e30f, mrow1 = -1e30f, lrow0 = 0.f, lrow1 = 0.f;
    float o[8][4];
#pragma unroll
    for (int nt = 0; nt < 8; nt++)
#pragma unroll
        for (int q = 0; q < 4; q++) o[nt][q] = 0.f;

    for (int kt = 0; kt < 16; kt++) {
        const int kv0 = kt * 64;
        __syncthreads();  // previous tile's PV done; sKP/sV reusable

        // Stage K and V tiles (fp16 copies)
#pragma unroll
        for (int i = 0; i < 4; i++) {
            int task = i * 128 + tid;
            int row = task >> 3, c4 = task & 7;
            *(uint4*)&sKP[row * ASH + c4 * 8] =
                *(const uint4*)(Kg + (size_t)(kv0 + row) * DKn + c4 * 8);
            *(uint4*)&sV[row * ASH + c4 * 8] =
                *(const uint4*)(Vg + (size_t)(kv0 + row) * DKn + c4 * 8);
        }
        if (tid < 64) smk[tid] = Mg[kv0 + tid];
        __syncthreads();

        // Bias prefetch (streaming; consumed after QK mma)
        float2 bb0[8], bb1[8];
#pragma unroll
        for (int nt = 0; nt < 8; nt++) {
            int col = kv0 + nt * 8 + ((lane & 3) << 1);
            bb0[nt] = ldcs2(Bg + (size_t)rq * Sn + col);
            bb1[nt] = ldcs2(Bg + (size_t)(rq + 8) * Sn + col);
        }

        // S = Q K^T
        float s[8][4];
#pragma unroll
        for (int nt = 0; nt < 8; nt++)
#pragma unroll
            for (int q = 0; q < 4; q++) s[nt][q] = 0.f;

#pragma unroll
        for (int ks = 0; ks < 4; ks++) {
            unsigned aq[4];
            ldsm4(aq[0], aq[1], aq[2], aq[3],
                  smaddr(&sQ[(warp * 16 + (lane & 15)) * ASH + ks * 16 + ((lane >> 4) << 3)]));
#pragma unroll
            for (int ntp = 0; ntp < 4; ntp++) {
                unsigned t0, t1, t2, t3;
                ldsm4(t0, t1, t2, t3,
                      smaddr(&sKP[(ntp * 16 + (lane & 7) + (((lane >> 4) & 1) << 3)) * ASH +
                                  ks * 16 + (((lane >> 3) & 1) << 3)]));
                mma_f16(s[2 * ntp], aq, t0, t1);
                mma_f16(s[2 * ntp + 1], aq, t2, t3);
            }
        }

        // bias + scale + mask + online softmax
        float rmax0 = -1e30f, rmax1 = -1e30f;
#pragma unroll
        for (int nt = 0; nt < 8; nt++) {
            int col = nt * 8 + ((lane & 3) << 1);
            int k0ok = smk[col], k1ok = smk[col + 1];
            float v0 = (mq0 & k0ok) ? (s[nt][0] + bb0[nt].x) * 0.125f : -1e9f;
            float v1 = (mq0 & k1ok) ? (s[nt][1] + bb0[nt].y) * 0.125f : -1e9f;
            float v2 = (mq1 & k0ok) ? (s[nt][2] + bb1[nt].x) * 0.125f : -1e9f;
            float v3 = (mq1 & k1ok) ? (s[nt][3] + bb1[nt].y) * 0.125f : -1e9f;
            s[nt][0] = v0; s[nt][1] = v1; s[nt][2] = v2; s[nt][3] = v3;
            rmax0 = fmaxf(rmax0, fmaxf(v0, v1));
            rmax1 = fmaxf(rmax1, fmaxf(v2, v3));
        }
        rmax0 = fmaxf(rmax0, __shfl_xor_sync(0xffffffffu, rmax0, 1));
        rmax0 = fmaxf(rmax0, __shfl_xor_sync(0xffffffffu, rmax0, 2));
        rmax1 = fmaxf(rmax1, __shfl_xor_sync(0xffffffffu, rmax1, 1));
        rmax1 = fmaxf(rmax1, __shfl_xor_sync(0xffffffffu, rmax1, 2));

        float mnew0 = fmaxf(mrow0, rmax0), mnew1 = fmaxf(mrow1, rmax1);
        float alpha0 = __expf(mrow0 - mnew0), alpha1 = __expf(mrow1 - mnew1);
        mrow0 = mnew0; mrow1 = mnew1;

        float sum0 = 0.f, sum1 = 0.f;
#pragma unroll
        for (int nt = 0; nt < 8; nt++) {
            s[nt][0] = __expf(s[nt][0] - mnew0); sum0 += s[nt][0];
            s[nt][1] = __expf(s[nt][1] - mnew0); sum0 += s[nt][1];
            s[nt][2] = __expf(s[nt][2] - mnew1); sum1 += s[nt][2];
            s[nt][3] = __expf(s[nt][3] - mnew1); sum1 += s[nt][3];
        }
        sum0 += __shfl_xor_sync(0xffffffffu, sum0, 1);
        sum0 += __shfl_xor_sync(0xffffffffu, sum0, 2);
        sum1 += __shfl_xor_sync(0xffffffffu, sum1, 1);
        sum1 += __shfl_xor_sync(0xffffffffu, sum1, 2);
        lrow0 = lrow0 * alpha0 + sum0;
        lrow1 = lrow1 * alpha1 + sum1;

#pragma unroll
        for (int nt = 0; nt < 8; nt++) {
            o[nt][0] *= alpha0; o[nt][1] *= alpha0;
            o[nt][2] *= alpha1; o[nt][3] *= alpha1;
        }

        __syncthreads();  // all warps done reading sKP (K) -> overwrite with P
#pragma unroll
        for (int nt = 0; nt < 8; nt++) {
            int col = nt * 8 + ((lane & 3) << 1);
            *(__half2*)&sKP[rq * ASH + col] = __floats2half2_rn(s[nt][0], s[nt][1]);
            *(__half2*)&sKP[(rq + 8) * ASH + col] = __floats2half2_rn(s[nt][2], s[nt][3]);
        }
        __syncwarp();  // PV A-frags read only this warp's own rows

        // O += P V   (B-fragments via ldmatrix.trans on row-major V)
#pragma unroll
        for (int ks = 0; ks < 4; ks++) {
            unsigned ap[4];
            ldsm4(ap[0], ap[1], ap[2], ap[3],
                  smaddr(&sKP[(warp * 16 + (lane & 15)) * ASH + ks * 16 + ((lane >> 4) << 3)]));
#pragma unroll
            for (int ntp = 0; ntp < 4; ntp++) {
                unsigned t0, t1, t2, t3;
                ldsm4t(t0, t1, t2, t3,
                       smaddr(&sV[(ks * 16 + (lane & 7) + (((lane >> 3) & 1) << 3)) * ASH +
                                  ntp * 16 + (((lane >> 4) & 1) << 3)]));
                mma_f16(o[2 * ntp], ap, t0, t1);
                mma_f16(o[2 * ntp + 1], ap, t2, t3);
            }
        }
    }

    // Epilogue
    float inv0 = 1.f / lrow0, inv1 = 1.f / lrow1;
    float* Cg = g_ctx + ((size_t)b * Sn + q0) * Dn + h * DKn;
#pragma unroll
    for (int nt = 0; nt < 8; nt++) {
        int col = nt * 8 + ((lane & 3) << 1);
        *(float2*)(Cg + (size_t)rq * Dn + col) =
            make_float2(o[nt][0] * inv0, o[nt][1] * inv0);
        *(float2*)(Cg + (size_t)(rq + 8) * Dn + col) =
            make_float2(o[nt][2] * inv1, o[nt][3] * inv1);
    }
}

// ---------------------------------------------------------------------------
// kernel_launch
// ---------------------------------------------------------------------------
extern "C" void kernel_launch(void* const* d_in, const int* in_sizes, int n_in,
                              void* d_out, int out_size) {
    (void)in_sizes; (void)n_in; (void)out_size;
    const float* query = (const float*)d_in[0];
    const float* key   = (const float*)d_in[1];
    const float* value = (const float*)d_in[2];
    const float* bias  = (const float*)d_in[3];
    const void*  mask  = d_in[4];
    const float* Wq = (const float*)d_in[5];
    const float* bq = (const float*)d_in[6];
    const float* Wk = (const float*)d_in[7];
    const float* bk = (const float*)d_in[8];
    const float* Wv = (const float*)d_in[9];
    const float* bv = (const float*)d_in[10];
    const float* Wo = (const float*)d_in[11];
    const float* bo = (const float*)d_in[12];
    float* out = (float*)d_out;

    mask_prep_kernel<<<1, 256>>>(mask);
    bias_tr_kernel<<<dim3(Sn / 128, Sn, Bn), 256>>>(bias);
    qkv_proj_kernel<<<dim3(Dn / 128, (Bn * Sn) / 128, 3), 256>>>(
        query, key, value, Wq, Wk, Wv, bq, bk, bv);
    attn_kernel<<<dim3(Sn / 64, Hn, Bn), 128>>>();
    outproj_kernel<<<dim3(Dn / 128, (Bn * Sn) / 128, 1), 256>>>(Wo, bo, out);
}

// round 9
// speedup vs baseline: 1.8767x; 1.1570x over previous
#include <cuda_runtime.h>
#include <cuda_fp16.h>

// ---------------------------------------------------------------------------
// Problem constants
// ---------------------------------------------------------------------------
#define Bn  4
#define Sn  1024
#define Dn  1024
#define Hn  16
#define DKn 64

// ---------------------------------------------------------------------------
// Device scratch (everything on the mma path stored fp16)
// ---------------------------------------------------------------------------
__device__ __half g_q[(size_t)Bn * Hn * Sn * DKn];     // [B,H,S,DK]
__device__ __half g_k[(size_t)Bn * Hn * Sn * DKn];
__device__ __half g_v[(size_t)Bn * Hn * Sn * DKn];
__device__ __half g_biasT[(size_t)Bn * Hn * Sn * Sn];  // [B,H,S,S] fp16
__device__ __half g_ctx[(size_t)Bn * Sn * Dn];         // [B,S,D] fp16
__device__ __half g_xq[(size_t)Bn * Sn * Dn];          // fp16 inputs
__device__ __half g_xk[(size_t)Bn * Sn * Dn];
__device__ __half g_xv[(size_t)Bn * Sn * Dn];
__device__ __half g_wq[(size_t)Dn * Dn];               // fp16 weights
__device__ __half g_wk[(size_t)Dn * Dn];
__device__ __half g_wv[(size_t)Dn * Dn];
__device__ __half g_wo[(size_t)Dn * Dn];
__device__ unsigned char g_mask[Bn * Sn];

// ---------------------------------------------------------------------------
// Helpers
// ---------------------------------------------------------------------------
__device__ __forceinline__ unsigned h2u(__half2 h) {
    return *reinterpret_cast<unsigned*>(&h);
}

__device__ __forceinline__ unsigned smaddr(const void* p) {
    return (unsigned)__cvta_generic_to_shared(p);
}

__device__ __forceinline__ void ldsm4(unsigned& r0, unsigned& r1, unsigned& r2,
                                      unsigned& r3, unsigned addr) {
    asm volatile("ldmatrix.sync.aligned.m8n8.x4.shared.b16 {%0,%1,%2,%3}, [%4];"
                 : "=r"(r0), "=r"(r1), "=r"(r2), "=r"(r3) : "r"(addr));
}

__device__ __forceinline__ void ldsm4t(unsigned& r0, unsigned& r1, unsigned& r2,
                                       unsigned& r3, unsigned addr) {
    asm volatile("ldmatrix.sync.aligned.m8n8.x4.trans.shared.b16 {%0,%1,%2,%3}, [%4];"
                 : "=r"(r0), "=r"(r1), "=r"(r2), "=r"(r3) : "r"(addr));
}

__device__ __forceinline__ void mma_f16(float c[4], const unsigned a[4],
                                        unsigned b0, unsigned b1) {
    asm volatile(
        "mma.sync.aligned.m16n8k16.row.col.f32.f16.f16.f32 "
        "{%0,%1,%2,%3},{%4,%5,%6,%7},{%8,%9},{%0,%1,%2,%3};\n"
        : "+f"(c[0]), "+f"(c[1]), "+f"(c[2]), "+f"(c[3])
        : "r"(a[0]), "r"(a[1]), "r"(a[2]), "r"(a[3]), "r"(b0), "r"(b1));
}

// ---------------------------------------------------------------------------
// Mask normalization
// ---------------------------------------------------------------------------
__global__ void mask_prep_kernel(const void* __restrict__ mraw) {
    __shared__ int flags[2];
    if (threadIdx.x < 2) flags[threadIdx.x] = 0;
    __syncthreads();
    const unsigned* w = (const unsigned*)mraw;
    for (int i = threadIdx.x; i < 1024; i += blockDim.x) {
        unsigned v = w[i];
        if (v > 1u) flags[0] = 1;
        if (v != 0u && v != 0x3F800000u) flags[1] = 1;
    }
    __syncthreads();
    int mode = flags[0] ? (flags[1] ? 0 : 2) : 1;
    for (int i = threadIdx.x; i < Bn * Sn; i += blockDim.x) {
        unsigned char v;
        if (mode == 1)      v = (((const int*)mraw)[i] != 0);
        else if (mode == 2) v = (((const float*)mraw)[i] != 0.f);
        else                v = (((const unsigned char*)mraw)[i] != 0);
        g_mask[i] = v;
    }
}

// ---------------------------------------------------------------------------
// fp32 -> fp16 conversion for inputs + weights (one pass, vectorized)
// grid.z: 0..2 inputs (4M elems), 3..6 weights (1M elems)
// ---------------------------------------------------------------------------
__global__ void f2h_kernel(const float* __restrict__ xq, const float* __restrict__ xk,
                           const float* __restrict__ xv, const float* __restrict__ wq,
                           const float* __restrict__ wk, const float* __restrict__ wv,
                           const float* __restrict__ wo) {
    int z = blockIdx.z;
    const float* src;
    __half* dst;
    int n4;
    switch (z) {
        case 0: src = xq; dst = g_xq; n4 = (Bn * Sn * Dn) / 4; break;
        case 1: src = xk; dst = g_xk; n4 = (Bn * Sn * Dn) / 4; break;
        case 2: src = xv; dst = g_xv; n4 = (Bn * Sn * Dn) / 4; break;
        case 3: src = wq; dst = g_wq; n4 = (Dn * Dn) / 4; break;
        case 4: src = wk; dst = g_wk; n4 = (Dn * Dn) / 4; break;
        case 5: src = wv; dst = g_wv; n4 = (Dn * Dn) / 4; break;
        default: src = wo; dst = g_wo; n4 = (Dn * Dn) / 4; break;
    }
    for (int i = blockIdx.x * blockDim.x + threadIdx.x; i < n4;
         i += gridDim.x * blockDim.x) {
        float4 v = ((const float4*)src)[i];
        ((uint2*)dst)[i] = make_uint2(h2u(__floats2half2_rn(v.x, v.y)),
                                      h2u(__floats2half2_rn(v.z, v.w)));
    }
}

// ---------------------------------------------------------------------------
// Bias transpose [B,S,S,H] fp32 -> [B,H,S,S] fp16
// ---------------------------------------------------------------------------
__global__ void bias_tr_kernel(const float* __restrict__ bias) {
    __shared__ float t[16][129];
    const int k0 = blockIdx.x * 128;
    const int q  = blockIdx.y;
    const int b  = blockIdx.z;
    const float* src = bias + ((size_t)(b * Sn + q) * Sn + k0) * Hn;
    for (int i = threadIdx.x; i < 2048; i += 256) {
        int kk = i >> 4, hh = i & 15;
        t[hh][kk] = __ldcs(src + i);
    }
    __syncthreads();
    for (int i = threadIdx.x; i < 1024; i += 256) {
        int hh = i >> 6, kk2 = i & 63;
        __half2 v = __floats2half2_rn(t[hh][kk2 * 2], t[hh][kk2 * 2 + 1]);
        __half* dst = &g_biasT[((size_t)(b * Hn + hh) * Sn + q) * Sn + k0 + kk2 * 2];
        __stcs((__half2*)dst, v);
    }
}

// ---------------------------------------------------------------------------
// TN GEMM fp16 (fp16 operands at rest): C[M,N] = A[M,1024]*W[N,1024]^T + bias
// 128x128x32 tile, 256 threads, 8 warps (2m x 4n), single-buffered smem,
// register staging (uint4 of 8 halves), ldmatrix, m16n8k16 mma (fp32 accum).
// ---------------------------------------------------------------------------
#define GSH 40   // smem stride in halves (80B rows: ldmatrix conflict-free)

template <int MODE>
__device__ __forceinline__ void gemm_h16(const __half* __restrict__ A,
                                         const __half* __restrict__ W,
                                         const float* __restrict__ bvec,
                                         void* __restrict__ outv) {
    __shared__ __half sA[128 * GSH];
    __shared__ __half sW[128 * GSH];

    const int tid  = threadIdx.x;
    const int lane = tid & 31;
    const int warp = tid >> 5;
    const int wm = (warp >> 2) * 64;
    const int wn = (warp & 3) * 32;
    const int m0 = blockIdx.y * 128;
    const int n0 = blockIdx.x * 128;

    float acc[4][4][4];
#pragma unroll
    for (int mt = 0; mt < 4; mt++)
#pragma unroll
        for (int nt = 0; nt < 4; nt++)
#pragma unroll
            for (int q = 0; q < 4; q++) acc[mt][nt][q] = 0.f;

    const int srow = tid >> 2;          // staging row (per i: +64? no: task-based)
    uint4 ra[2], rw[2];
#pragma unroll
    for (int i = 0; i < 2; i++) {
        int task = i * 256 + tid;
        int row = task >> 2, c8 = task & 3;
        ra[i] = *(const uint4*)(A + (size_t)(m0 + row) * Dn + c8 * 8);
        rw[i] = *(const uint4*)(W + (size_t)(n0 + row) * Dn + c8 * 8);
    }
    (void)srow;

    for (int kt = 0; kt < 32; kt++) {
#pragma unroll
        for (int i = 0; i < 2; i++) {
            int task = i * 256 + tid;
            int row = task >> 2, c8 = task & 3;
            *(uint4*)&sA[row * GSH + c8 * 8] = ra[i];
            *(uint4*)&sW[row * GSH + c8 * 8] = rw[i];
        }
        __syncthreads();

        if (kt < 31) {
            int kb = (kt + 1) * 32;
#pragma unroll
            for (int i = 0; i < 2; i++) {
                int task = i * 256 + tid;
                int row = task >> 2, c8 = task & 3;
                ra[i] = *(const uint4*)(A + (size_t)(m0 + row) * Dn + kb + c8 * 8);
                rw[i] = *(const uint4*)(W + (size_t)(n0 + row) * Dn + kb + c8 * 8);
            }
        }

#pragma unroll
        for (int ks = 0; ks < 2; ks++) {
            const int koff = ks * 16 + ((lane >> 4) << 3);
            unsigned afr[4][4];
#pragma unroll
            for (int mt = 0; mt < 4; mt++)
                ldsm4(afr[mt][0], afr[mt][1], afr[mt][2], afr[mt][3],
                      smaddr(&sA[(wm + mt * 16 + (lane & 15)) * GSH + koff]));
            unsigned bfr[4][2];
#pragma unroll
            for (int ntp = 0; ntp < 2; ntp++) {
                unsigned t0, t1, t2, t3;
                ldsm4(t0, t1, t2, t3,
                      smaddr(&sW[(wn + ntp * 16 + (lane & 7) + (((lane >> 4) & 1) << 3)) * GSH +
                                 ks * 16 + (((lane >> 3) & 1) << 3)]));
                bfr[2 * ntp][0] = t0; bfr[2 * ntp][1] = t1;
                bfr[2 * ntp + 1][0] = t2; bfr[2 * ntp + 1][1] = t3;
            }
#pragma unroll
            for (int mt = 0; mt < 4; mt++)
#pragma unroll
                for (int nt = 0; nt < 4; nt++)
                    mma_f16(acc[mt][nt], afr[mt], bfr[nt][0], bfr[nt][1]);
        }
        __syncthreads();
    }

#pragma unroll
    for (int mt = 0; mt < 4; mt++) {
#pragma unroll
        for (int nt = 0; nt < 4; nt++) {
            int row = m0 + wm + mt * 16 + (lane >> 2);
            int col = n0 + wn + nt * 8 + ((lane & 3) << 1);
            float b0 = bvec[col], b1 = bvec[col + 1];
            float v00 = acc[mt][nt][0] + b0, v01 = acc[mt][nt][1] + b1;
            float v10 = acc[mt][nt][2] + b0, v11 = acc[mt][nt][3] + b1;
            if (MODE == 0) {
                float* out = (float*)outv;
                *(float2*)(out + (size_t)row * Dn + col) = make_float2(v00, v01);
                *(float2*)(out + (size_t)(row + 8) * Dn + col) = make_float2(v10, v11);
            } else {
                __half* out = (__half*)outv;
                int hh = col >> 6, dk = col & 63;
                int bb0 = row >> 10, s0 = row & 1023;
                int r8 = row + 8;
                int bb1 = r8 >> 10, s1 = r8 & 1023;
                *(__half2*)(out + ((size_t)(bb0 * Hn + hh) * Sn + s0) * DKn + dk) =
                    __floats2half2_rn(v00, v01);
                *(__half2*)(out + ((size_t)(bb1 * Hn + hh) * Sn + s1) * DKn + dk) =
                    __floats2half2_rn(v10, v11);
            }
        }
    }
}

__global__ void __launch_bounds__(256) qkv_proj_kernel(
    const float* __restrict__ bq, const float* __restrict__ bk,
    const float* __restrict__ bv) {
    int z = blockIdx.z;
    const __half* A = (z == 0) ? g_xq : (z == 1) ? g_xk : g_xv;
    const __half* W = (z == 0) ? g_wq : (z == 1) ? g_wk : g_wv;
    const float* bb = (z == 0) ? bq : (z == 1) ? bk : bv;
    __half* out = (z == 0) ? g_q : (z == 1) ? g_k : g_v;
    gemm_h16<1>(A, W, bb, out);
}

__global__ void __launch_bounds__(256) outproj_kernel(
    const float* __restrict__ bo, float* __restrict__ out) {
    gemm_h16<0>(g_ctx, g_wo, bo, out);
}

// ---------------------------------------------------------------------------
// Flash attention fp16: 64 q-rows, 128 threads (4 warps).
// Bias (fp16) prefetched at tile top — covered by K/V staging + 2 syncs.
// ---------------------------------------------------------------------------
#define ASH 72   // smem stride in halves (144B rows: ldmatrix conflict-free)

__global__ void __launch_bounds__(128) attn_kernel() {
    __shared__ __half sQ[64 * ASH];
    __shared__ __half sKP[64 * ASH];   // K tile, reused as P tile
    __shared__ __half sV[64 * ASH];
    __shared__ unsigned char smk[64];

    const int qt = blockIdx.x, h = blockIdx.y, b = blockIdx.z;
    const int q0 = qt * 64;
    const int tid = threadIdx.x, lane = tid & 31, warp = tid >> 5;
    const int rq = warp * 16 + (lane >> 2);

    const size_t headoff = (size_t)(b * Hn + h) * Sn * DKn;
    const __half* Qg = g_q + headoff + (size_t)q0 * DKn;
    const __half* Kg = g_k + headoff;
    const __half* Vg = g_v + headoff;
    const __half* Bg = g_biasT + ((size_t)(b * Hn + h) * Sn + q0) * Sn;
    const unsigned char* Mg = g_mask + b * Sn;

    // Load Q tile (fp16, straight copy)
#pragma unroll
    for (int i = 0; i < 4; i++) {
        int task = i * 128 + tid;
        int row = task >> 3, c4 = task & 7;
        *(uint4*)&sQ[row * ASH + c4 * 8] = *(const uint4*)(Qg + (size_t)row * DKn + c4 * 8);
    }

    const int mq0 = Mg[q0 + rq];
    const int mq1 = Mg[q0 + rq + 8];

    float mrow0 = -1e30f, mrow1 = -1e30f, lrow0 = 0.f, lrow1 = 0.f;
    float o[8][4];
#pragma unroll
    for (int nt = 0; nt < 8; nt++)
#pragma unroll
        for (int q = 0; q < 4; q++) o[nt][q] = 0.f;

    for (int kt = 0; kt < 16; kt++) {
        const int kv0 = kt * 64;

        // Bias prefetch (fp16, streaming) at tile top — the K/V staging phase
        // below (gmem loads + 2 syncs) covers its DRAM latency.
        __half2 bb0[8], bb1[8];
#pragma unroll
        for (int nt = 0; nt < 8; nt++) {
            int col = kv0 + nt * 8 + ((lane & 3) << 1);
            bb0[nt] = __ldcs((const __half2*)(Bg + (size_t)rq * Sn + col));
            bb1[nt] = __ldcs((const __half2*)(Bg + (size_t)(rq + 8) * Sn + col));
        }

        __syncthreads();  // previous tile's PV done; sKP/sV reusable

        // Stage K and V tiles (fp16 copies)
#pragma unroll
        for (int i = 0; i < 4; i++) {
            int task = i * 128 + tid;
            int row = task >> 3, c4 = task & 7;
            *(uint4*)&sKP[row * ASH + c4 * 8] =
                *(const uint4*)(Kg + (size_t)(kv0 + row) * DKn + c4 * 8);
            *(uint4*)&sV[row * ASH + c4 * 8] =
                *(const uint4*)(Vg + (size_t)(kv0 + row) * DKn + c4 * 8);
        }
        if (tid < 64) smk[tid] = Mg[kv0 + tid];
        __syncthreads();

        // S = Q K^T
        float s[8][4];
#pragma unroll
        for (int nt = 0; nt < 8; nt++)
#pragma unroll
            for (int q = 0; q < 4; q++) s[nt][q] = 0.f;

#pragma unroll
        for (int ks = 0; ks < 4; ks++) {
            unsigned aq[4];
            ldsm4(aq[0], aq[1], aq[2], aq[3],
                  smaddr(&sQ[(warp * 16 + (lane & 15)) * ASH + ks * 16 + ((lane >> 4) << 3)]));
#pragma unroll
            for (int ntp = 0; ntp < 4; ntp++) {
                unsigned t0, t1, t2, t3;
                ldsm4(t0, t1, t2, t3,
                      smaddr(&sKP[(ntp * 16 + (lane & 7) + (((lane >> 4) & 1) << 3)) * ASH +
                                  ks * 16 + (((lane >> 3) & 1) << 3)]));
                mma_f16(s[2 * ntp], aq, t0, t1);
                mma_f16(s[2 * ntp + 1], aq, t2, t3);
            }
        }

        // bias + scale + mask + online softmax
        float rmax0 = -1e30f, rmax1 = -1e30f;
#pragma unroll
        for (int nt = 0; nt < 8; nt++) {
            int col = nt * 8 + ((lane & 3) << 1);
            int k0ok = smk[col], k1ok = smk[col + 1];
            float2 f0 = __half22float2(bb0[nt]);
            float2 f1 = __half22float2(bb1[nt]);
            float v0 = (mq0 & k0ok) ? (s[nt][0] + f0.x) * 0.125f : -1e9f;
            float v1 = (mq0 & k1ok) ? (s[nt][1] + f0.y) * 0.125f : -1e9f;
            float v2 = (mq1 & k0ok) ? (s[nt][2] + f1.x) * 0.125f : -1e9f;
            float v3 = (mq1 & k1ok) ? (s[nt][3] + f1.y) * 0.125f : -1e9f;
            s[nt][0] = v0; s[nt][1] = v1; s[nt][2] = v2; s[nt][3] = v3;
            rmax0 = fmaxf(rmax0, fmaxf(v0, v1));
            rmax1 = fmaxf(rmax1, fmaxf(v2, v3));
        }
        rmax0 = fmaxf(rmax0, __shfl_xor_sync(0xffffffffu, rmax0, 1));
        rmax0 = fmaxf(rmax0, __shfl_xor_sync(0xffffffffu, rmax0, 2));
        rmax1 = fmaxf(rmax1, __shfl_xor_sync(0xffffffffu, rmax1, 1));
        rmax1 = fmaxf(rmax1, __shfl_xor_sync(0xffffffffu, rmax1, 2));

        float mnew0 = fmaxf(mrow0, rmax0), mnew1 = fmaxf(mrow1, rmax1);
        float alpha0 = __expf(mrow0 - mnew0), alpha1 = __expf(mrow1 - mnew1);
        mrow0 = mnew0; mrow1 = mnew1;

        float sum0 = 0.f, sum1 = 0.f;
#pragma unroll
        for (int nt = 0; nt < 8; nt++) {
            s[nt][0] = __expf(s[nt][0] - mnew0); sum0 += s[nt][0];
            s[nt][1] = __expf(s[nt][1] - mnew0); sum0 += s[nt][1];
            s[nt][2] = __expf(s[nt][2] - mnew1); sum1 += s[nt][2];
            s[nt][3] = __expf(s[nt][3] - mnew1); sum1 += s[nt][3];
        }
        sum0 += __shfl_xor_sync(0xffffffffu, sum0, 1);
        sum0 += __shfl_xor_sync(0xffffffffu, sum0, 2);
        sum1 += __shfl_xor_sync(0xffffffffu, sum1, 1);
        sum1 += __shfl_xor_sync(0xffffffffu, sum1, 2);
        lrow0 = lrow0 * alpha0 + sum0;
        lrow1 = lrow1 * alpha1 + sum1;

#pragma unroll
        for (int nt = 0; nt < 8; nt++) {
            o[nt][0] *= alpha0; o[nt][1] *= alpha0;
            o[nt][2] *= alpha1; o[nt][3] *= alpha1;
        }

        __syncthreads();  // all warps done reading sKP (K) -> overwrite with P
#pragma unroll
        for (int nt = 0; nt < 8; nt++) {
            int col = nt * 8 + ((lane & 3) << 1);
            *(__half2*)&sKP[rq * ASH + col] = __floats2half2_rn(s[nt][0], s[nt][1]);
            *(__half2*)&sKP[(rq + 8) * ASH + col] = __floats2half2_rn(s[nt][2], s[nt][3]);
        }
        __syncwarp();  // PV A-frags read only this warp's own rows

        // O += P V   (B-fragments via ldmatrix.trans on row-major V)
#pragma unroll
        for (int ks = 0; ks < 4; ks++) {
            unsigned ap[4];
            ldsm4(ap[0], ap[1], ap[2], ap[3],
                  smaddr(&sKP[(warp * 16 + (lane & 15)) * ASH + ks * 16 + ((lane >> 4) << 3)]));
#pragma unroll
            for (int ntp = 0; ntp < 4; ntp++) {
                unsigned t0, t1, t2, t3;
                ldsm4t(t0, t1, t2, t3,
                       smaddr(&sV[(ks * 16 + (lane & 7) + (((lane >> 3) & 1) << 3)) * ASH +
                                  ntp * 16 + (((lane >> 4) & 1) << 3)]));
                mma_f16(o[2 * ntp], ap, t0, t1);
                mma_f16(o[2 * ntp + 1], ap, t2, t3);
            }
        }
    }

    // Epilogue: normalize, write ctx fp16 [B,S,D]
    float inv0 = 1.f / lrow0, inv1 = 1.f / lrow1;
    __half* Cg = g_ctx + ((size_t)b * Sn + q0) * Dn + h * DKn;
#pragma unroll
    for (int nt = 0; nt < 8; nt++) {
        int col = nt * 8 + ((lane & 3) << 1);
        *(__half2*)(Cg + (size_t)rq * Dn + col) =
            __floats2half2_rn(o[nt][0] * inv0, o[nt][1] * inv0);
        *(__half2*)(Cg + (size_t)(rq + 8) * Dn + col) =
            __floats2half2_rn(o[nt][2] * inv1, o[nt][3] * inv1);
    }
}

// ---------------------------------------------------------------------------
// kernel_launch
// ---------------------------------------------------------------------------
extern "C" void kernel_launch(void* const* d_in, const int* in_sizes, int n_in,
                              void* d_out, int out_size) {
    (void)in_sizes; (void)n_in; (void)out_size;
    const float* query = (const float*)d_in[0];
    const float* key   = (const float*)d_in[1];
    const float* value = (const float*)d_in[2];
    const float* bias  = (const float*)d_in[3];
    const void*  mask  = d_in[4];
    const float* Wq = (const float*)d_in[5];
    const float* bq = (const float*)d_in[6];
    const float* Wk = (const float*)d_in[7];
    const float* bk = (const float*)d_in[8];
    const float* Wv = (const float*)d_in[9];
    const float* bv = (const float*)d_in[10];
    const float* Wo = (const float*)d_in[11];
    const float* bo = (const float*)d_in[12];
    float* out = (float*)d_out;

    mask_prep_kernel<<<1, 256>>>(mask);
    f2h_kernel<<<dim3(1024, 1, 7), 256>>>(query, key, value, Wq, Wk, Wv, Wo);
    bias_tr_kernel<<<dim3(Sn / 128, Sn, Bn), 256>>>(bias);
    qkv_proj_kernel<<<dim3(Dn / 128, (Bn * Sn) / 128, 3), 256>>>(bq, bk, bv);
    attn_kernel<<<dim3(Sn / 64, Hn, Bn), 128>>>();
    outproj_kernel<<<dim3(Dn / 128, (Bn * Sn) / 128, 1), 256>>>(bo, out);
}